// round 3
// baseline (speedup 1.0000x reference)
#include <cuda_runtime.h>
#include <cstdint>

// ---------------------------------------------------------------------------
// AutoconstraintModel: two MLP branches.
//  partner: per-node logit = wp2 . relu(Base[g] + node[i] @ Wm) + bp2
//           where Base[g] = cur[g]@Wp1[0:128] + glob[g]@Wp1[256:384] + bp1
//           and Wm = Wp1[128:256]   (algebraic 2.8x FLOP reduction vs naive)
//  label:   3-layer MLP on gathered [cur|partner|glob] per graph.
// fp32 exact math; packed fma.rn.f32x2 (k-paired partial sums) for 2x fp32.
// ---------------------------------------------------------------------------

#define DD 128

__device__ float g_base[8192 * 128];   // scratch: Base[B][128] (4 MB, static)

union F2 { unsigned long long u; float2 f; };

__device__ __forceinline__ void fma2(unsigned long long& d,
                                     unsigned long long a,
                                     unsigned long long b) {
    asm("fma.rn.f32x2 %0, %1, %2, %0;" : "+l"(d) : "l"(a), "l"(b));
}
__device__ __forceinline__ unsigned long long dup2(float w) {
    unsigned long long r;
    asm("mov.b64 %0, {%1, %1};" : "=l"(r) : "f"(w));
    return r;
}

// ===========================================================================
// Kernel A: Base[g][c] = bp1[c] + cur[g].Wp1[0:128][c] + glob[g].Wp1[256:384][c]
// 64 graphs / block, 256 threads (col = t&127, graph-half = t>>7).
// Activations staged transposed x_s[k][g] (stride 66), graphs paired in f32x2.
// ===========================================================================
__global__ void __launch_bounds__(256) base_kernel(
    const float* __restrict__ node, const float* __restrict__ glob,
    const float* __restrict__ Wp1, const float* __restrict__ bp1, int n_per)
{
    extern __shared__ float sm[];            // x_s: [256][66]
    const int t   = threadIdx.x;
    const int gg0 = blockIdx.x * 64;

    #pragma unroll
    for (int i = 0; i < 64; i++) {           // 64*256 floats
        int idx = t + i * 256;
        int g = idx >> 8, k = idx & 255;
        int gg = gg0 + g;
        float v = (k < 128)
            ? node[(size_t)((gg + 1) * n_per - 1) * DD + k]
            : glob[(size_t)gg * DD + (k - 128)];
        sm[k * 66 + g] = v;
    }
    __syncthreads();

    const int col = t & 127, half = t >> 7;
    F2 acc[16];
    #pragma unroll
    for (int p = 0; p < 16; p++) acc[p].f = make_float2(0.f, 0.f);

    #pragma unroll 4
    for (int k = 0; k < 256; k++) {
        int gk = (k < 128) ? k : (k + 128);  // skip the node-block rows of Wp1
        unsigned long long ww = dup2(Wp1[gk * 128 + col]);
        const float* xr = sm + k * 66 + half * 32;
        #pragma unroll
        for (int p = 0; p < 16; p++)
            fma2(acc[p].u, *(const unsigned long long*)(xr + 2 * p), ww);
    }
    float bias = bp1[col];
    #pragma unroll
    for (int p = 0; p < 16; p++) {
        int gg = gg0 + half * 32 + 2 * p;
        g_base[(size_t)gg * 128 + col]       = acc[p].f.x + bias;
        g_base[(size_t)(gg + 1) * 128 + col] = acc[p].f.y + bias;
    }
}

// ===========================================================================
// Kernel B (dominant): per graph g, H = relu(Base[g] + Node[64,128] @ Wm),
// logit = H @ wp2 + bp2. One block per graph, 128 threads.
// 8x8 register tile per thread; k-paired f32x2 accumulation (even/odd-k
// halves summed at the end). Wm transposed in smem with stride 130
// (conflict-free LDS.64 across 16 consecutive c-lanes).
// ===========================================================================
__global__ void __launch_bounds__(128) partner_kernel(
    const float* __restrict__ node, const float* __restrict__ Wp1,
    const float* __restrict__ Wp2, const float* __restrict__ bp2,
    float* __restrict__ out)
{
    extern __shared__ float sm[];
    float* Wt = sm;                      // [128][130]  Wt[c][k] = Wm[k][c]
    float* ns = sm + 128 * 130;          // [64][128]
    float* bs = ns + 64 * 128;           // [128] base
    float* w2 = bs + 128;                // [128] wp2

    const int g = blockIdx.x, t = threadIdx.x;

    {   // node tile: 8192 contiguous floats -> float4 coalesced
        const float4* src = (const float4*)(node + (size_t)g * 64 * 128);
        float4* dst = (float4*)ns;
        #pragma unroll
        for (int i = 0; i < 16; i++) dst[t + i * 128] = src[t + i * 128];
    }
    #pragma unroll 4
    for (int k = 0; k < 128; k++)        // transpose Wm into smem
        Wt[t * 130 + k] = Wp1[(128 + k) * 128 + t];

    bs[t] = g_base[(size_t)g * 128 + t];
    w2[t] = Wp2[t];
    __syncthreads();

    const int c0 = t & 15;               // 16 col-groups (cols c0 + 16j)
    const int r0 = (t >> 4) * 8;         // 8 row-groups (8 rows each)

    F2 acc[8][8];
    #pragma unroll
    for (int r = 0; r < 8; r++)
        #pragma unroll
        for (int j = 0; j < 8; j++) acc[r][j].f = make_float2(0.f, 0.f);

    const float* nrow = ns + r0 * 128;
    const float* wrow = Wt + c0 * 130;

    #pragma unroll 4
    for (int k = 0; k < 128; k += 2) {
        unsigned long long a[8], b[8];
        #pragma unroll
        for (int r = 0; r < 8; r++)
            a[r] = *(const unsigned long long*)(nrow + r * 128 + k);
        #pragma unroll
        for (int j = 0; j < 8; j++)
            b[j] = *(const unsigned long long*)(wrow + j * (16 * 130) + k);
        #pragma unroll
        for (int r = 0; r < 8; r++)
            #pragma unroll
            for (int j = 0; j < 8; j++)
                fma2(acc[r][j].u, a[r], b[j]);
    }

    // epilogue: combine k-halves, relu, dot with wp2, reduce over 16 lanes
    const float bp2v = bp2[0];
    float part[8];
    #pragma unroll
    for (int r = 0; r < 8; r++) {
        float s = 0.f;
        #pragma unroll
        for (int j = 0; j < 8; j++) {
            int c = c0 + j * 16;
            float v = acc[r][j].f.x + acc[r][j].f.y + bs[c];
            s += fmaxf(v, 0.f) * w2[c];
        }
        part[r] = s;
    }
    #pragma unroll
    for (int off = 8; off; off >>= 1)
        #pragma unroll
        for (int r = 0; r < 8; r++)
            part[r] += __shfl_down_sync(0xffffffffu, part[r], off, 16);
    if (c0 == 0) {
        #pragma unroll
        for (int r = 0; r < 8; r++)
            out[(size_t)g * 64 + r0 + r] = part[r] + bp2v;
    }
}

// ===========================================================================
// Kernel C: label MLP, 64 graphs / block, 256 threads.
// X gathered transposed [384][66]; layers use same graph-paired f32x2 scheme.
// h2 is written back into the x_s region (disjoint from h_s reads).
// ===========================================================================
__global__ void __launch_bounds__(256) label_kernel(
    const float* __restrict__ node, const float* __restrict__ glob,
    const float* __restrict__ Wl1, const float* __restrict__ bl1,
    const float* __restrict__ Wl2, const float* __restrict__ bl2,
    const float* __restrict__ Wl3, const float* __restrict__ bl3,
    const int* __restrict__ pgi, const int* __restrict__ pni,
    int n_per, int NL, float* __restrict__ out)
{
    extern __shared__ float sm[];
    float* xs = sm;                  // [384][66], later reused as h2 [128][66]
    float* hs = xs + 384 * 66;       // [128][66]
    float* w3 = hs + 128 * 66;       // [128*NL]
    float* b3 = w3 + 128 * NL;       // [NL]

    const int t  = threadIdx.x;
    const int b0 = blockIdx.x * 64;

    #pragma unroll
    for (int i = 0; i < 96; i++) {   // gather 64 * 384 floats
        int idx = t + i * 256;
        int row = idx >> 7, k = idx & 127;
        int g = row / 3, s = row - g * 3;
        int pg = pgi[b0 + g];
        const float* src;
        if (s == 0)      src = node + (size_t)((pg + 1) * n_per - 1) * DD;
        else if (s == 1) src = node + (size_t)pni[b0 + g] * DD;
        else             src = glob + (size_t)pg * DD;
        xs[(s * 128 + k) * 66 + g] = src[k];
    }
    for (int i = t; i < 128 * NL; i += 256) w3[i] = Wl3[i];
    if (t < NL) b3[t] = bl3[t];
    __syncthreads();

    const int col = t & 127, half = t >> 7;

    {   // layer 1: K = 384
        F2 acc[16];
        #pragma unroll
        for (int p = 0; p < 16; p++) acc[p].f = make_float2(0.f, 0.f);
        #pragma unroll 2
        for (int k = 0; k < 384; k++) {
            unsigned long long ww = dup2(Wl1[k * 128 + col]);
            const float* xr = xs + k * 66 + half * 32;
            #pragma unroll
            for (int p = 0; p < 16; p++)
                fma2(acc[p].u, *(const unsigned long long*)(xr + 2 * p), ww);
        }
        float b = bl1[col];
        #pragma unroll
        for (int p = 0; p < 16; p++) {
            int g = half * 32 + 2 * p;
            hs[col * 66 + g]     = fmaxf(acc[p].f.x + b, 0.f);
            hs[col * 66 + g + 1] = fmaxf(acc[p].f.y + b, 0.f);
        }
    }
    __syncthreads();

    {   // layer 2: K = 128, read hs, write h2 into xs (disjoint regions)
        F2 acc[16];
        #pragma unroll
        for (int p = 0; p < 16; p++) acc[p].f = make_float2(0.f, 0.f);
        #pragma unroll 2
        for (int k = 0; k < 128; k++) {
            unsigned long long ww = dup2(Wl2[k * 128 + col]);
            const float* xr = hs + k * 66 + half * 32;
            #pragma unroll
            for (int p = 0; p < 16; p++)
                fma2(acc[p].u, *(const unsigned long long*)(xr + 2 * p), ww);
        }
        float b = bl2[col];
        #pragma unroll
        for (int p = 0; p < 16; p++) {
            int g = half * 32 + 2 * p;
            xs[col * 66 + g]     = fmaxf(acc[p].f.x + b, 0.f);
            xs[col * 66 + g + 1] = fmaxf(acc[p].f.y + b, 0.f);
        }
    }
    __syncthreads();

    // layer 3: [64, NL] outputs
    for (int o = t; o < 64 * NL; o += 256) {
        int g = o / NL, nl = o - g * NL;
        float a = b3[nl];
        #pragma unroll 4
        for (int k = 0; k < 128; k++)
            a += xs[k * 66 + g] * w3[k * NL + nl];
        out[(size_t)(b0 + g) * NL + nl] = a;
    }
}

// ===========================================================================
extern "C" void kernel_launch(void* const* d_in, const int* in_sizes, int n_in,
                              void* d_out, int out_size)
{
    const float* node = (const float*)d_in[0];
    const float* glob = (const float*)d_in[1];
    const float* Wp1  = (const float*)d_in[2];
    const float* bp1  = (const float*)d_in[3];
    const float* Wp2  = (const float*)d_in[4];
    const float* bp2  = (const float*)d_in[5];
    const float* Wl1  = (const float*)d_in[6];
    const float* bl1  = (const float*)d_in[7];
    const float* Wl2  = (const float*)d_in[8];
    const float* bl2  = (const float*)d_in[9];
    const float* Wl3  = (const float*)d_in[10];
    const float* bl3  = (const float*)d_in[11];
    const int*   pgi  = (const int*)d_in[12];
    const int*   pni  = (const int*)d_in[13];

    const int N     = in_sizes[0] / DD;
    const int B     = in_sizes[1] / DD;
    const int n_per = N / B;                 // 64 (static per problem)
    const int NL    = in_sizes[11];          // 14

    float* out = (float*)d_out;

    const size_t smA = (size_t)(256 * 66) * sizeof(float);
    const size_t smB = (size_t)(128 * 130 + 64 * 128 + 256) * sizeof(float);
    const size_t smC = (size_t)(384 * 66 + 128 * 66 + 128 * NL + NL) * sizeof(float);

    cudaFuncSetAttribute(base_kernel,    cudaFuncAttributeMaxDynamicSharedMemorySize, (int)smA);
    cudaFuncSetAttribute(partner_kernel, cudaFuncAttributeMaxDynamicSharedMemorySize, (int)smB);
    cudaFuncSetAttribute(label_kernel,   cudaFuncAttributeMaxDynamicSharedMemorySize, (int)smC);

    base_kernel<<<B / 64, 256, smA>>>(node, glob, Wp1, bp1, n_per);
    label_kernel<<<B / 64, 256, smC>>>(node, glob, Wl1, bl1, Wl2, bl2,
                                       Wl3, bl3, pgi, pni, n_per, NL,
                                       out + (size_t)N);
    partner_kernel<<<B, 128, smB>>>(node, Wp1, Wp2, bp2, out);
}

// round 5
// speedup vs baseline: 1.9825x; 1.9825x over previous
#include <cuda_runtime.h>
#include <cuda_bf16.h>
#include <cstdint>

// ---------------------------------------------------------------------------
// AutoconstraintModel on GB300 (harness target sm_103 — NO 'a' features,
// so tcgen05 is unavailable; tensor work goes through mma.sync HMMA).
//  partner (dominant): logit = w2 . relu(Base[g] + Node @ Wm) + bp2
//      -> mma.sync m16n8k16 bf16, 2-term split precision:
//         D = Ahi.Bhi + Ahi.Blo + Alo.Bhi (fp32 accum, lo.lo dropped ~2^-18)
//  base:  Base[g] = cur@Wp1[0:128] + glob@Wp1[256:384] + bp1 (fp32x2, W staged)
//  label: 3-layer MLP per graph (fp32x2, W staged in smem chunks)
// ---------------------------------------------------------------------------

#define DD 128

__device__ float g_base[8192 * 128];   // Base[B][128] scratch (4 MB static)

// ============================ fp32x2 helpers ===============================
union F2 { unsigned long long u; float2 f; };

__device__ __forceinline__ void fma2(unsigned long long& d,
                                     unsigned long long a,
                                     unsigned long long b) {
    asm("fma.rn.f32x2 %0, %1, %2, %0;" : "+l"(d) : "l"(a), "l"(b));
}
__device__ __forceinline__ unsigned long long dup2(float w) {
    unsigned long long r;
    asm("mov.b64 %0, {%1, %1};" : "=l"(r) : "f"(w));
    return r;
}

// ============================ HMMA helpers =================================
__device__ __forceinline__ void mma_bf16(float* c, const uint32_t* a,
                                         uint32_t b0, uint32_t b1) {
    asm volatile(
        "mma.sync.aligned.m16n8k16.row.col.f32.bf16.bf16.f32 "
        "{%0,%1,%2,%3}, {%4,%5,%6,%7}, {%8,%9}, {%0,%1,%2,%3};"
        : "+f"(c[0]), "+f"(c[1]), "+f"(c[2]), "+f"(c[3])
        : "r"(a[0]), "r"(a[1]), "r"(a[2]), "r"(a[3]), "r"(b0), "r"(b1));
}

// fp32 pair -> (hi bf16x2, lo-residual bf16x2); low half = first element
__device__ __forceinline__ void split2(float x, float y,
                                       uint32_t& hi, uint32_t& lo) {
    __nv_bfloat162 h = __floats2bfloat162_rn(x, y);
    float2 hf = __bfloat1622float2(h);
    __nv_bfloat162 r = __floats2bfloat162_rn(x - hf.x, y - hf.y);
    hi = *reinterpret_cast<uint32_t*>(&h);
    lo = *reinterpret_cast<uint32_t*>(&r);
}

// ===========================================================================
// base kernel: Base[g][c] = bp1[c] + cur.W1a + glob.W1c ; 32 graphs/block.
// ===========================================================================
__global__ void __launch_bounds__(256) base_kernel(
    const float* __restrict__ node, const float* __restrict__ glob,
    const float* __restrict__ Wp1, const float* __restrict__ bp1, int n_per)
{
    extern __shared__ float sm[];
    float* xs = sm;                    // [256][34]
    float* Ws = sm + 256 * 34;         // [64][128]

    const int t  = threadIdx.x;
    const int b0 = blockIdx.x * 32;

    #pragma unroll
    for (int i = 0; i < 32; i++) {     // k = t, graph = i : coalesced
        float v = (t < 128)
            ? node[(size_t)((b0 + i + 1) * n_per - 1) * DD + t]
            : glob[(size_t)(b0 + i) * DD + (t - 128)];
        xs[t * 34 + i] = v;
    }

    const int col = t & 127, hf = t >> 7;
    F2 acc[8];
    #pragma unroll
    for (int p = 0; p < 8; p++) acc[p].f = make_float2(0.f, 0.f);

    for (int c = 0; c < 4; c++) {
        __syncthreads();
        #pragma unroll
        for (int j = 0; j < 32; j++) { // load 64x128 W chunk
            int idx = t + j * 256;
            int kk = idx >> 7, cc = idx & 127;
            int rg = c * 64 + kk;
            Ws[kk * 128 + cc] = Wp1[(size_t)(rg < 128 ? rg : rg + 128) * 128 + cc];
        }
        __syncthreads();
        #pragma unroll 4
        for (int kk = 0; kk < 64; kk++) {
            unsigned long long ww = dup2(Ws[kk * 128 + col]);
            const float* xr = xs + (c * 64 + kk) * 34 + hf * 16;
            #pragma unroll
            for (int p = 0; p < 8; p++)
                fma2(acc[p].u, *(const unsigned long long*)(xr + 2 * p), ww);
        }
    }
    float bias = bp1[col];
    #pragma unroll
    for (int p = 0; p < 8; p++) {
        int g = b0 + hf * 16 + 2 * p;
        g_base[(size_t)g * 128 + col]       = acc[p].f.x + bias;
        g_base[(size_t)(g + 1) * 128 + col] = acc[p].f.y + bias;
    }
}

// ===========================================================================
// label kernel: 32 graphs/block, W staged in smem chunks.
// ===========================================================================
__global__ void __launch_bounds__(256) label_kernel(
    const float* __restrict__ node, const float* __restrict__ glob,
    const float* __restrict__ Wl1, const float* __restrict__ bl1,
    const float* __restrict__ Wl2, const float* __restrict__ bl2,
    const float* __restrict__ Wl3, const float* __restrict__ bl3,
    const int* __restrict__ pgi, const int* __restrict__ pni,
    int n_per, int NL, float* __restrict__ out)
{
    extern __shared__ float sm[];
    float* xs = sm;                    // [384][34] -> later h2 [128][34]
    float* hs = xs + 384 * 34;         // [128][34]
    float* Ws = hs + 128 * 34;         // [64][128] chunk
    float* w3 = Ws + 64 * 128;         // [128*NL]
    float* b3 = w3 + 128 * NL;         // [NL]

    const int t  = threadIdx.x;
    const int b0 = blockIdx.x * 32;

    #pragma unroll
    for (int i = 0; i < 48; i++) {     // gather 32*384 floats
        int idx = t + i * 256;
        int row = idx >> 7, k = idx & 127;
        int g = row / 3, s = row - g * 3;
        int pg = pgi[b0 + g];
        const float* src;
        if (s == 0)      src = node + (size_t)((pg + 1) * n_per - 1) * DD;
        else if (s == 1) src = node + (size_t)pni[b0 + g] * DD;
        else             src = glob + (size_t)pg * DD;
        xs[(s * 128 + k) * 34 + g] = src[k];
    }
    for (int i = t; i < 128 * NL; i += 256) w3[i] = Wl3[i];
    if (t < NL) b3[t] = bl3[t];

    const int col = t & 127, hf = t >> 7;

    {   // layer 1: K=384, 6 chunks
        F2 acc[8];
        #pragma unroll
        for (int p = 0; p < 8; p++) acc[p].f = make_float2(0.f, 0.f);
        for (int c = 0; c < 6; c++) {
            __syncthreads();
            #pragma unroll
            for (int j = 0; j < 32; j++) {
                int idx = t + j * 256;
                int kk = idx >> 7, cc = idx & 127;
                Ws[kk * 128 + cc] = Wl1[(size_t)(c * 64 + kk) * 128 + cc];
            }
            __syncthreads();
            #pragma unroll 4
            for (int kk = 0; kk < 64; kk++) {
                unsigned long long ww = dup2(Ws[kk * 128 + col]);
                const float* xr = xs + (c * 64 + kk) * 34 + hf * 16;
                #pragma unroll
                for (int p = 0; p < 8; p++)
                    fma2(acc[p].u, *(const unsigned long long*)(xr + 2 * p), ww);
            }
        }
        float b = bl1[col];
        __syncthreads();
        #pragma unroll
        for (int p = 0; p < 8; p++) {
            int g = hf * 16 + 2 * p;
            hs[col * 34 + g]     = fmaxf(acc[p].f.x + b, 0.f);
            hs[col * 34 + g + 1] = fmaxf(acc[p].f.y + b, 0.f);
        }
    }

    {   // layer 2: K=128, 2 chunks; reads hs, writes h2 into xs region
        F2 acc[8];
        #pragma unroll
        for (int p = 0; p < 8; p++) acc[p].f = make_float2(0.f, 0.f);
        for (int c = 0; c < 2; c++) {
            __syncthreads();
            #pragma unroll
            for (int j = 0; j < 32; j++) {
                int idx = t + j * 256;
                int kk = idx >> 7, cc = idx & 127;
                Ws[kk * 128 + cc] = Wl2[(size_t)(c * 64 + kk) * 128 + cc];
            }
            __syncthreads();
            #pragma unroll 4
            for (int kk = 0; kk < 64; kk++) {
                unsigned long long ww = dup2(Ws[kk * 128 + col]);
                const float* xr = hs + (c * 64 + kk) * 34 + hf * 16;
                #pragma unroll
                for (int p = 0; p < 8; p++)
                    fma2(acc[p].u, *(const unsigned long long*)(xr + 2 * p), ww);
            }
        }
        float b = bl2[col];
        __syncthreads();
        #pragma unroll
        for (int p = 0; p < 8; p++) {
            int g = hf * 16 + 2 * p;
            xs[col * 34 + g]     = fmaxf(acc[p].f.x + b, 0.f);
            xs[col * 34 + g + 1] = fmaxf(acc[p].f.y + b, 0.f);
        }
    }
    __syncthreads();

    for (int o = t; o < 32 * NL; o += 256) {   // layer 3: [32, NL]
        int g = o / NL, nl = o - g * NL;
        float a = b3[nl];
        #pragma unroll 4
        for (int k = 0; k < 128; k++)
            a += xs[k * 34 + g] * w3[k * NL + nl];
        out[(size_t)(b0 + g) * NL + nl] = a;
    }
}

// ===========================================================================
// partner kernel (dominant): mma.sync bf16 split-precision GEMM + epilogue.
// Block tile: 128 rows (2 graphs) x 128 cols, K = 128. 8 warps:
//   warp w: rows [(w&3)*32, +32), cols [(w>>2)*64, +64); warp tile 32x64.
// B (Wm hi/lo) staged in smem (stride 136 bf16 -> conflict-free LDS frags).
// A fragments loaded straight from gmem as float2 and split in registers.
// ===========================================================================
#define BSTR 136                       // B smem row stride in bf16 elements

__global__ void __launch_bounds__(256, 2) partner_kernel(
    const float* __restrict__ node, const float* __restrict__ Wp1,
    const float* __restrict__ Wp2, const float* __restrict__ bp2,
    float* __restrict__ out)
{
    extern __shared__ char smc[];
    __nv_bfloat16* Bhi = (__nv_bfloat16*)smc;           // [128][BSTR]
    __nv_bfloat16* Blo = Bhi + 128 * BSTR;              // [128][BSTR]
    float* base2 = (float*)(Blo + 128 * BSTR);          // [2][128]
    float* w2s   = base2 + 256;                         // [128]
    float* srow  = w2s + 128;                           // [128][2]

    const int t = threadIdx.x;
    const size_t rowbase = (size_t)blockIdx.x * 128;

    // ---- stage B[n][k] = Wm[k][n] = Wp1[128+k][n], split hi/lo ----
    #pragma unroll
    for (int i = 0; i < 64; i++) {
        int idx = t + i * 256;                  // 16384 elements
        int k = idx >> 7, n = idx & 127;        // coalesced read over n
        float v = Wp1[(size_t)(128 + k) * 128 + n];
        __nv_bfloat16 h = __float2bfloat16(v);
        Bhi[n * BSTR + k] = h;
        Blo[n * BSTR + k] = __float2bfloat16(v - __bfloat162float(h));
    }
    base2[t] = g_base[rowbase * 128 / 64 + t];  // == blockIdx.x*256 + t
    if (t < 128) w2s[t] = Wp2[t];
    __syncthreads();

    const int w = t >> 5, l = t & 31;
    const int lr = l >> 2, lc = l & 3;          // frag row / quad col
    const int mrow0 = (w & 3) * 32;             // warp row band
    const int ncol0 = (w >> 2) * 64;            // warp col band
    const int gh = (w & 3) >> 1;                // graph half (rows>=64)

    const float* Ab = node + (rowbase + mrow0 + lr) * DD + lc * 2;

    float acc[2][8][4];
    #pragma unroll
    for (int mt = 0; mt < 2; mt++)
        #pragma unroll
        for (int nt = 0; nt < 8; nt++)
            #pragma unroll
            for (int j = 0; j < 4; j++) acc[mt][nt][j] = 0.f;

    #pragma unroll 2
    for (int kc = 0; kc < 8; kc++) {
        const int kb = kc * 16;
        uint32_t Ah[2][4], Al[2][4];
        #pragma unroll
        for (int mt = 0; mt < 2; mt++) {
            const float* p = Ab + mt * 16 * DD + kb;
            float2 v0 = *(const float2*)(p);
            float2 v1 = *(const float2*)(p + 8 * DD);
            float2 v2 = *(const float2*)(p + 8);
            float2 v3 = *(const float2*)(p + 8 * DD + 8);
            split2(v0.x, v0.y, Ah[mt][0], Al[mt][0]);
            split2(v1.x, v1.y, Ah[mt][1], Al[mt][1]);
            split2(v2.x, v2.y, Ah[mt][2], Al[mt][2]);
            split2(v3.x, v3.y, Ah[mt][3], Al[mt][3]);
        }
        #pragma unroll
        for (int nt = 0; nt < 8; nt++) {
            const __nv_bfloat16* bp = Bhi + (ncol0 + nt * 8 + lr) * BSTR
                                          + kb + lc * 2;
            uint32_t bh0 = *(const uint32_t*)bp;
            uint32_t bh1 = *(const uint32_t*)(bp + 8);
            const __nv_bfloat16* bq = bp + 128 * BSTR;
            uint32_t bl0 = *(const uint32_t*)bq;
            uint32_t bl1 = *(const uint32_t*)(bq + 8);
            #pragma unroll
            for (int mt = 0; mt < 2; mt++) {
                mma_bf16(acc[mt][nt], Ah[mt], bh0, bh1);
                mma_bf16(acc[mt][nt], Ah[mt], bl0, bl1);
                mma_bf16(acc[mt][nt], Al[mt], bh0, bh1);
            }
        }
    }

    // ---- epilogue: relu(acc + base) . w2, quad-reduce, combine colgroups ----
    float pr[2][2] = {{0.f, 0.f}, {0.f, 0.f}};
    #pragma unroll
    for (int nt = 0; nt < 8; nt++) {
        int c0 = ncol0 + nt * 8 + lc * 2;
        float wa = w2s[c0],  wb = w2s[c0 + 1];
        float ba = base2[gh * 128 + c0], bb = base2[gh * 128 + c0 + 1];
        #pragma unroll
        for (int mt = 0; mt < 2; mt++) {
            pr[mt][0] += fmaxf(acc[mt][nt][0] + ba, 0.f) * wa
                       + fmaxf(acc[mt][nt][1] + bb, 0.f) * wb;
            pr[mt][1] += fmaxf(acc[mt][nt][2] + ba, 0.f) * wa
                       + fmaxf(acc[mt][nt][3] + bb, 0.f) * wb;
        }
    }
    #pragma unroll
    for (int o = 1; o <= 2; o <<= 1) {
        pr[0][0] += __shfl_xor_sync(0xffffffffu, pr[0][0], o);
        pr[0][1] += __shfl_xor_sync(0xffffffffu, pr[0][1], o);
        pr[1][0] += __shfl_xor_sync(0xffffffffu, pr[1][0], o);
        pr[1][1] += __shfl_xor_sync(0xffffffffu, pr[1][1], o);
    }
    if (lc == 0) {
        const int cg = w >> 2;
        srow[(mrow0 + lr) * 2 + cg]      = pr[0][0];
        srow[(mrow0 + lr + 8) * 2 + cg]  = pr[0][1];
        srow[(mrow0 + 16 + lr) * 2 + cg] = pr[1][0];
        srow[(mrow0 + 24 + lr) * 2 + cg] = pr[1][1];
    }
    __syncthreads();
    if (t < 128)
        out[rowbase + t] = srow[t * 2] + srow[t * 2 + 1] + bp2[0];
}

// ===========================================================================
extern "C" void kernel_launch(void* const* d_in, const int* in_sizes, int n_in,
                              void* d_out, int out_size)
{
    const float* node = (const float*)d_in[0];
    const float* glob = (const float*)d_in[1];
    const float* Wp1  = (const float*)d_in[2];
    const float* bp1  = (const float*)d_in[3];
    const float* Wp2  = (const float*)d_in[4];
    const float* bp2  = (const float*)d_in[5];
    const float* Wl1  = (const float*)d_in[6];
    const float* bl1  = (const float*)d_in[7];
    const float* Wl2  = (const float*)d_in[8];
    const float* bl2  = (const float*)d_in[9];
    const float* Wl3  = (const float*)d_in[10];
    const float* bl3  = (const float*)d_in[11];
    const int*   pgi  = (const int*)d_in[12];
    const int*   pni  = (const int*)d_in[13];

    const int N     = in_sizes[0] / DD;
    const int B     = in_sizes[1] / DD;
    const int n_per = N / B;            // 64
    const int NL    = in_sizes[11];     // 14

    float* out = (float*)d_out;

    const size_t smA = (size_t)(256 * 34 + 64 * 128) * sizeof(float);
    const size_t smC = (size_t)(384 * 34 + 128 * 34 + 64 * 128 + 128 * NL + NL)
                       * sizeof(float);
    const size_t smP = (size_t)(2 * 128 * BSTR) * sizeof(__nv_bfloat16)
                     + (size_t)(256 + 128 + 256) * sizeof(float);

    cudaFuncSetAttribute(base_kernel,    cudaFuncAttributeMaxDynamicSharedMemorySize, (int)smA);
    cudaFuncSetAttribute(label_kernel,   cudaFuncAttributeMaxDynamicSharedMemorySize, (int)smC);
    cudaFuncSetAttribute(partner_kernel, cudaFuncAttributeMaxDynamicSharedMemorySize, (int)smP);

    base_kernel<<<B / 32, 256, smA>>>(node, glob, Wp1, bp1, n_per);
    label_kernel<<<B / 32, 256, smC>>>(node, glob, Wl1, bl1, Wl2, bl2,
                                       Wl3, bl3, pgi, pni, n_per, NL,
                                       out + (size_t)N);
    partner_kernel<<<N / 128, 256, smP>>>(node, Wp1, Wp2, bp2, out);
}

// round 6
// speedup vs baseline: 2.3632x; 1.1920x over previous
#include <cuda_runtime.h>
#include <cuda_bf16.h>
#include <cstdint>

// ---------------------------------------------------------------------------
// AutoconstraintModel on GB300 (harness target sm_103 — no tcgen05; tensor
// work via mma.sync m16n8k16 bf16 with 2-term split precision:
//   D = Ahi.Bhi + Ahi.Blo + Alo.Bhi   (fp32 accum, lo.lo dropped ~2^-18)
//  partner (dominant): persistent CTAs, B resident in smem (staged once),
//      A streamed via cp.async 4-slice ring (prefetch distance 3).
//  base:  HMMA split GEMM [B,256]@[256,128] -> g_base.
//  label: 3-layer MLP per graph (fp32x2, W staged in smem chunks).
// ---------------------------------------------------------------------------

#define DD 128
#define BSTR 136      // partner B smem row stride (bf16)
#define KSTR 264      // base B smem row stride (bf16), K=256
#define RING 4        // A ring slices
#define ASTR 20       // A slice row stride (floats, 16B-aligned rows)

__device__ float g_base[8192 * 128];   // Base[B][128] scratch (4 MB static)

// ============================ fp32x2 helpers (label) =======================
union F2 { unsigned long long u; float2 f; };

__device__ __forceinline__ void fma2(unsigned long long& d,
                                     unsigned long long a,
                                     unsigned long long b) {
    asm("fma.rn.f32x2 %0, %1, %2, %0;" : "+l"(d) : "l"(a), "l"(b));
}
__device__ __forceinline__ unsigned long long dup2(float w) {
    unsigned long long r;
    asm("mov.b64 %0, {%1, %1};" : "=l"(r) : "f"(w));
    return r;
}

// ============================ HMMA helpers =================================
__device__ __forceinline__ void mma_bf16(float* c, const uint32_t* a,
                                         uint32_t b0, uint32_t b1) {
    asm volatile(
        "mma.sync.aligned.m16n8k16.row.col.f32.bf16.bf16.f32 "
        "{%0,%1,%2,%3}, {%4,%5,%6,%7}, {%8,%9}, {%0,%1,%2,%3};"
        : "+f"(c[0]), "+f"(c[1]), "+f"(c[2]), "+f"(c[3])
        : "r"(a[0]), "r"(a[1]), "r"(a[2]), "r"(a[3]), "r"(b0), "r"(b1));
}

__device__ __forceinline__ void split2(float x, float y,
                                       uint32_t& hi, uint32_t& lo) {
    __nv_bfloat162 h = __floats2bfloat162_rn(x, y);
    float2 hf = __bfloat1622float2(h);
    __nv_bfloat162 r = __floats2bfloat162_rn(x - hf.x, y - hf.y);
    hi = *reinterpret_cast<uint32_t*>(&h);
    lo = *reinterpret_cast<uint32_t*>(&r);
}

__device__ __forceinline__ uint32_t smem_u32(const void* p) {
    uint32_t a;
    asm("{ .reg .u64 t; cvta.to.shared.u64 t, %1; cvt.u32.u64 %0, t; }"
        : "=r"(a) : "l"(p));
    return a;
}

#define CP_COMMIT() asm volatile("cp.async.commit_group;" ::: "memory")
#define CP_WAIT2()  asm volatile("cp.async.wait_group 2;" ::: "memory")

// ===========================================================================
// base kernel (HMMA): g_base[g][c] = bp1[c] + [cur_g|glob_g](256) @ W1ac.
// 64 blocks x 128 graphs. B = W1ac split (hi/lo) staged in smem, K=256.
// ===========================================================================
__global__ void __launch_bounds__(256) base_kernel(
    const float* __restrict__ node, const float* __restrict__ glob,
    const float* __restrict__ Wp1, const float* __restrict__ bp1, int n_per)
{
    extern __shared__ char smc[];
    __nv_bfloat16* Bhi = (__nv_bfloat16*)smc;            // [128 n][KSTR k]
    __nv_bfloat16* Blo = Bhi + 128 * KSTR;
    float* bias = (float*)(Blo + 128 * KSTR);            // [128]

    const int t = threadIdx.x;

    #pragma unroll
    for (int i = 0; i < 128; i++) {                      // 32768 elements
        int idx = t + i * 256;
        int k = idx >> 7, n = idx & 127;                 // coalesced over n
        float v = Wp1[(size_t)(k < 128 ? k : k + 128) * 128 + n];
        __nv_bfloat16 h = __float2bfloat16(v);
        Bhi[n * KSTR + k] = h;
        Blo[n * KSTR + k] = __float2bfloat16(v - __bfloat162float(h));
    }
    if (t < 128) bias[t] = bp1[t];
    __syncthreads();

    const int w = t >> 5, l = t & 31;
    const int lr = l >> 2, lc = l & 3;
    const int mrow0 = (w & 3) * 32;
    const int ncol0 = (w >> 2) * 64;
    const int g0 = blockIdx.x * 128;

    float acc[2][8][4];
    #pragma unroll
    for (int mt = 0; mt < 2; mt++)
        #pragma unroll
        for (int nt = 0; nt < 8; nt++)
            #pragma unroll
            for (int j = 0; j < 4; j++) acc[mt][nt][j] = 0.f;

    #pragma unroll 2
    for (int kc = 0; kc < 16; kc++) {
        const int kb = kc * 16;
        uint32_t Ah[2][4], Al[2][4];
        #pragma unroll
        for (int mt = 0; mt < 2; mt++) {
            int ga = g0 + mrow0 + mt * 16 + lr;
            int gb = ga + 8;
            const float *pa, *pb;
            if (kb < 128) {
                pa = node + (size_t)((ga + 1) * n_per - 1) * DD + kb + lc * 2;
                pb = node + (size_t)((gb + 1) * n_per - 1) * DD + kb + lc * 2;
            } else {
                pa = glob + (size_t)ga * DD + (kb - 128) + lc * 2;
                pb = glob + (size_t)gb * DD + (kb - 128) + lc * 2;
            }
            float2 v0 = *(const float2*)pa;
            float2 v1 = *(const float2*)pb;
            float2 v2 = *(const float2*)(pa + 8);
            float2 v3 = *(const float2*)(pb + 8);
            split2(v0.x, v0.y, Ah[mt][0], Al[mt][0]);
            split2(v1.x, v1.y, Ah[mt][1], Al[mt][1]);
            split2(v2.x, v2.y, Ah[mt][2], Al[mt][2]);
            split2(v3.x, v3.y, Ah[mt][3], Al[mt][3]);
        }
        #pragma unroll
        for (int nt = 0; nt < 8; nt++) {
            const __nv_bfloat16* bp = Bhi + (ncol0 + nt * 8 + lr) * KSTR
                                          + kb + lc * 2;
            uint32_t bh0 = *(const uint32_t*)bp;
            uint32_t bh1 = *(const uint32_t*)(bp + 8);
            const __nv_bfloat16* bq = bp + 128 * KSTR;
            uint32_t bl0 = *(const uint32_t*)bq;
            uint32_t bl1 = *(const uint32_t*)(bq + 8);
            #pragma unroll
            for (int mt = 0; mt < 2; mt++) {
                mma_bf16(acc[mt][nt], Ah[mt], bh0, bh1);
                mma_bf16(acc[mt][nt], Ah[mt], bl0, bl1);
                mma_bf16(acc[mt][nt], Al[mt], bh0, bh1);
            }
        }
    }

    #pragma unroll
    for (int mt = 0; mt < 2; mt++) {
        int ga = g0 + mrow0 + mt * 16 + lr;
        #pragma unroll
        for (int nt = 0; nt < 8; nt++) {
            int col = ncol0 + nt * 8 + lc * 2;
            float ba = bias[col], bb = bias[col + 1];
            *(float2*)(g_base + (size_t)ga * 128 + col) =
                make_float2(acc[mt][nt][0] + ba, acc[mt][nt][1] + bb);
            *(float2*)(g_base + (size_t)(ga + 8) * 128 + col) =
                make_float2(acc[mt][nt][2] + ba, acc[mt][nt][3] + bb);
        }
    }
}

// ===========================================================================
// label kernel: 32 graphs/block, W staged in smem chunks (unchanged, ~25us).
// ===========================================================================
__global__ void __launch_bounds__(256) label_kernel(
    const float* __restrict__ node, const float* __restrict__ glob,
    const float* __restrict__ Wl1, const float* __restrict__ bl1,
    const float* __restrict__ Wl2, const float* __restrict__ bl2,
    const float* __restrict__ Wl3, const float* __restrict__ bl3,
    const int* __restrict__ pgi, const int* __restrict__ pni,
    int n_per, int NL, float* __restrict__ out)
{
    extern __shared__ float sm[];
    float* xs = sm;                    // [384][34] -> later h2 [128][34]
    float* hs = xs + 384 * 34;         // [128][34]
    float* Ws = hs + 128 * 34;         // [64][128] chunk
    float* w3 = Ws + 64 * 128;         // [128*NL]
    float* b3 = w3 + 128 * NL;         // [NL]

    const int t  = threadIdx.x;
    const int b0 = blockIdx.x * 32;

    #pragma unroll
    for (int i = 0; i < 48; i++) {     // gather 32*384 floats
        int idx = t + i * 256;
        int row = idx >> 7, k = idx & 127;
        int g = row / 3, s = row - g * 3;
        int pg = pgi[b0 + g];
        const float* src;
        if (s == 0)      src = node + (size_t)((pg + 1) * n_per - 1) * DD;
        else if (s == 1) src = node + (size_t)pni[b0 + g] * DD;
        else             src = glob + (size_t)pg * DD;
        xs[(s * 128 + k) * 34 + g] = src[k];
    }
    for (int i = t; i < 128 * NL; i += 256) w3[i] = Wl3[i];
    if (t < NL) b3[t] = bl3[t];

    const int col = t & 127, hf = t >> 7;

    {   // layer 1: K=384, 6 chunks
        F2 acc[8];
        #pragma unroll
        for (int p = 0; p < 8; p++) acc[p].f = make_float2(0.f, 0.f);
        for (int c = 0; c < 6; c++) {
            __syncthreads();
            #pragma unroll
            for (int j = 0; j < 32; j++) {
                int idx = t + j * 256;
                int kk = idx >> 7, cc = idx & 127;
                Ws[kk * 128 + cc] = Wl1[(size_t)(c * 64 + kk) * 128 + cc];
            }
            __syncthreads();
            #pragma unroll 4
            for (int kk = 0; kk < 64; kk++) {
                unsigned long long ww = dup2(Ws[kk * 128 + col]);
                const float* xr = xs + (c * 64 + kk) * 34 + hf * 16;
                #pragma unroll
                for (int p = 0; p < 8; p++)
                    fma2(acc[p].u, *(const unsigned long long*)(xr + 2 * p), ww);
            }
        }
        float b = bl1[col];
        __syncthreads();
        #pragma unroll
        for (int p = 0; p < 8; p++) {
            int g = hf * 16 + 2 * p;
            hs[col * 34 + g]     = fmaxf(acc[p].f.x + b, 0.f);
            hs[col * 34 + g + 1] = fmaxf(acc[p].f.y + b, 0.f);
        }
    }

    {   // layer 2: K=128, 2 chunks
        F2 acc[8];
        #pragma unroll
        for (int p = 0; p < 8; p++) acc[p].f = make_float2(0.f, 0.f);
        for (int c = 0; c < 2; c++) {
            __syncthreads();
            #pragma unroll
            for (int j = 0; j < 32; j++) {
                int idx = t + j * 256;
                int kk = idx >> 7, cc = idx & 127;
                Ws[kk * 128 + cc] = Wl2[(size_t)(c * 64 + kk) * 128 + cc];
            }
            __syncthreads();
            #pragma unroll 4
            for (int kk = 0; kk < 64; kk++) {
                unsigned long long ww = dup2(Ws[kk * 128 + col]);
                const float* xr = hs + (c * 64 + kk) * 34 + hf * 16;
                #pragma unroll
                for (int p = 0; p < 8; p++)
                    fma2(acc[p].u, *(const unsigned long long*)(xr + 2 * p), ww);
            }
        }
        float b = bl2[col];
        __syncthreads();
        #pragma unroll
        for (int p = 0; p < 8; p++) {
            int g = hf * 16 + 2 * p;
            xs[col * 34 + g]     = fmaxf(acc[p].f.x + b, 0.f);
            xs[col * 34 + g + 1] = fmaxf(acc[p].f.y + b, 0.f);
        }
    }
    __syncthreads();

    for (int o = t; o < 32 * NL; o += 256) {   // layer 3
        int g = o / NL, nl = o - g * NL;
        float a = b3[nl];
        #pragma unroll 4
        for (int k = 0; k < 128; k++)
            a += xs[k * 34 + g] * w3[k * NL + nl];
        out[(size_t)(b0 + g) * NL + nl] = a;
    }
}

// ===========================================================================
// partner kernel (dominant): persistent HMMA split GEMM.
//  - B (Wm hi/lo) staged ONCE per CTA in smem.
//  - A fp32 streamed via cp.async into a 4-slice ring (prefetch distance 3).
//  - Per tile (128 rows = 2 graphs): 8 k-chunks, 24 HMMA/warp each;
//    epilogue relu(D+base).w2 thread-local, quad shfl-reduce, smem combine.
// ===========================================================================
__global__ void __launch_bounds__(256, 2) partner_kernel(
    const float* __restrict__ node, const float* __restrict__ Wp1,
    const float* __restrict__ Wp2, const float* __restrict__ bp2,
    float* __restrict__ out, int ntiles)
{
    extern __shared__ char smc[];
    __nv_bfloat16* Bhi = (__nv_bfloat16*)smc;            // [128][BSTR]
    __nv_bfloat16* Blo = Bhi + 128 * BSTR;               // [128][BSTR]
    float* Asl   = (float*)(Blo + 128 * BSTR);           // [RING][128][ASTR]
    float* base2 = Asl + RING * 128 * ASTR;              // [256]
    float* w2s   = base2 + 256;                          // [128]
    float* srow  = w2s + 128;                            // [128][2]

    const int t = threadIdx.x;
    const uint32_t asl_u32 = smem_u32(Asl);

    // ---- stage B[n][k] = Wm[k][n] split hi/lo (once per CTA) ----
    #pragma unroll
    for (int i = 0; i < 64; i++) {
        int idx = t + i * 256;
        int k = idx >> 7, n = idx & 127;
        float v = Wp1[(size_t)(128 + k) * 128 + n];
        __nv_bfloat16 h = __float2bfloat16(v);
        Bhi[n * BSTR + k] = h;
        Blo[n * BSTR + k] = __float2bfloat16(v - __bfloat162float(h));
    }
    if (t < 128) w2s[t] = Wp2[t];
    const float bp2v = bp2[0];

    const int w = t >> 5, l = t & 31;
    const int lr = l >> 2, lc = l & 3;
    const int mrow0 = (w & 3) * 32;
    const int ncol0 = (w >> 2) * 64;
    const int gh = (w & 3) >> 1;

    const int ntloc = (ntiles - (int)blockIdx.x + (int)gridDim.x - 1)
                      / (int)gridDim.x;
    const int nch = ntloc * 8;

    const int row_a = t >> 2;              // cp.async task mapping
    const int c4_a  = (t & 3) * 4;

    auto issue_chunk = [&](int c) {
        int tile = (int)blockIdx.x + (c >> 3) * (int)gridDim.x;
        size_t rb = (size_t)tile * 128;
        int kb = (c & 7) * 16;
        int s = c & (RING - 1);
        #pragma unroll
        for (int q = 0; q < 2; q++) {
            int row = row_a + q * 64;
            const float* src = node + (rb + row) * DD + kb + c4_a;
            uint32_t dst = asl_u32
                + (uint32_t)(((s * 128 + row) * ASTR + c4_a) * 4);
            asm volatile("cp.async.cg.shared.global [%0], [%1], 16;"
                         :: "r"(dst), "l"(src));
        }
    };

    #pragma unroll
    for (int c = 0; c < 3; c++) {          // prologue: 3 groups in flight
        if (c < nch) issue_chunk(c);
        CP_COMMIT();
    }

    float acc[2][8][4];

    for (int c = 0; c < nch; c++) {
        CP_WAIT2();
        __syncthreads();                   // slice (c&3) visible to all

        const int tile = (int)blockIdx.x + (c >> 3) * (int)gridDim.x;
        const int kc = c & 7, s = c & (RING - 1);

        if (kc == 0) {
            base2[t] = g_base[(size_t)tile * 256 + t];
            #pragma unroll
            for (int mt = 0; mt < 2; mt++)
                #pragma unroll
                for (int nt = 0; nt < 8; nt++)
                    #pragma unroll
                    for (int j = 0; j < 4; j++) acc[mt][nt][j] = 0.f;
        }

        if (c + 3 < nch) issue_chunk(c + 3);
        CP_COMMIT();

        // ---- A frags from ring slice, split hi/lo in regs ----
        uint32_t Ah[2][4], Al[2][4];
        const float* ab = Asl + (s * 128 + mrow0 + lr) * ASTR + lc * 2;
        #pragma unroll
        for (int mt = 0; mt < 2; mt++) {
            const float* p = ab + mt * 16 * ASTR;
            float2 v0 = *(const float2*)(p);
            float2 v1 = *(const float2*)(p + 8 * ASTR);
            float2 v2 = *(const float2*)(p + 8);
            float2 v3 = *(const float2*)(p + 8 * ASTR + 8);
            split2(v0.x, v0.y, Ah[mt][0], Al[mt][0]);
            split2(v1.x, v1.y, Ah[mt][1], Al[mt][1]);
            split2(v2.x, v2.y, Ah[mt][2], Al[mt][2]);
            split2(v3.x, v3.y, Ah[mt][3], Al[mt][3]);
        }

        const int kb = kc * 16;
        #pragma unroll
        for (int nt = 0; nt < 8; nt++) {
            const __nv_bfloat16* bp = Bhi + (ncol0 + nt * 8 + lr) * BSTR
                                          + kb + lc * 2;
            uint32_t bh0 = *(const uint32_t*)bp;
            uint32_t bh1 = *(const uint32_t*)(bp + 8);
            const __nv_bfloat16* bq = bp + 128 * BSTR;
            uint32_t bl0 = *(const uint32_t*)bq;
            uint32_t bl1 = *(const uint32_t*)(bq + 8);
            #pragma unroll
            for (int mt = 0; mt < 2; mt++) {
                mma_bf16(acc[mt][nt], Ah[mt], bh0, bh1);
                mma_bf16(acc[mt][nt], Ah[mt], bl0, bl1);
                mma_bf16(acc[mt][nt], Al[mt], bh0, bh1);
            }
        }

        if (kc == 7) {
            // ---- epilogue: relu(acc+base).w2, quad-reduce, combine ----
            float pr[2][2] = {{0.f, 0.f}, {0.f, 0.f}};
            #pragma unroll
            for (int nt = 0; nt < 8; nt++) {
                int c0 = ncol0 + nt * 8 + lc * 2;
                float wa = w2s[c0], wb = w2s[c0 + 1];
                float ba = base2[gh * 128 + c0], bb = base2[gh * 128 + c0 + 1];
                #pragma unroll
                for (int mt = 0; mt < 2; mt++) {
                    pr[mt][0] += fmaxf(acc[mt][nt][0] + ba, 0.f) * wa
                               + fmaxf(acc[mt][nt][1] + bb, 0.f) * wb;
                    pr[mt][1] += fmaxf(acc[mt][nt][2] + ba, 0.f) * wa
                               + fmaxf(acc[mt][nt][3] + bb, 0.f) * wb;
                }
            }
            #pragma unroll
            for (int o = 1; o <= 2; o <<= 1) {
                pr[0][0] += __shfl_xor_sync(0xffffffffu, pr[0][0], o);
                pr[0][1] += __shfl_xor_sync(0xffffffffu, pr[0][1], o);
                pr[1][0] += __shfl_xor_sync(0xffffffffu, pr[1][0], o);
                pr[1][1] += __shfl_xor_sync(0xffffffffu, pr[1][1], o);
            }
            if (lc == 0) {
                const int cg = w >> 2;
                srow[(mrow0 + lr) * 2 + cg]      = pr[0][0];
                srow[(mrow0 + lr + 8) * 2 + cg]  = pr[0][1];
                srow[(mrow0 + 16 + lr) * 2 + cg] = pr[1][0];
                srow[(mrow0 + 24 + lr) * 2 + cg] = pr[1][1];
            }
            __syncthreads();
            if (t < 128)
                out[(size_t)tile * 128 + t] =
                    srow[t * 2] + srow[t * 2 + 1] + bp2v;
        }
    }
}

// ===========================================================================
extern "C" void kernel_launch(void* const* d_in, const int* in_sizes, int n_in,
                              void* d_out, int out_size)
{
    const float* node = (const float*)d_in[0];
    const float* glob = (const float*)d_in[1];
    const float* Wp1  = (const float*)d_in[2];
    const float* bp1  = (const float*)d_in[3];
    const float* Wp2  = (const float*)d_in[4];
    const float* bp2  = (const float*)d_in[5];
    const float* Wl1  = (const float*)d_in[6];
    const float* bl1  = (const float*)d_in[7];
    const float* Wl2  = (const float*)d_in[8];
    const float* bl2  = (const float*)d_in[9];
    const float* Wl3  = (const float*)d_in[10];
    const float* bl3  = (const float*)d_in[11];
    const int*   pgi  = (const int*)d_in[12];
    const int*   pni  = (const int*)d_in[13];

    const int N     = in_sizes[0] / DD;
    const int B     = in_sizes[1] / DD;
    const int n_per = N / B;            // 64
    const int NL    = in_sizes[11];     // 14
    const int ntiles = N / 128;         // 4096

    float* out = (float*)d_out;

    const size_t smBase = (size_t)(2 * 128 * KSTR) * sizeof(__nv_bfloat16)
                        + 128 * sizeof(float);
    const size_t smC = (size_t)(384 * 34 + 128 * 34 + 64 * 128 + 128 * NL + NL)
                       * sizeof(float);
    const size_t smP = (size_t)(2 * 128 * BSTR) * sizeof(__nv_bfloat16)
                     + (size_t)(RING * 128 * ASTR + 256 + 128 + 256)
                       * sizeof(float);

    cudaFuncSetAttribute(base_kernel,    cudaFuncAttributeMaxDynamicSharedMemorySize, (int)smBase);
    cudaFuncSetAttribute(label_kernel,   cudaFuncAttributeMaxDynamicSharedMemorySize, (int)smC);
    cudaFuncSetAttribute(partner_kernel, cudaFuncAttributeMaxDynamicSharedMemorySize, (int)smP);

    base_kernel<<<B / 128, 256, smBase>>>(node, glob, Wp1, bp1, n_per);
    label_kernel<<<B / 32, 256, smC>>>(node, glob, Wl1, bl1, Wl2, bl2,
                                       Wl3, bl3, pgi, pni, n_per, NL,
                                       out + (size_t)N);

    int grid = 2 * 148;                 // persistent, 2 CTAs/SM
    if (grid > ntiles) grid = ntiles;
    partner_kernel<<<grid, 256, smP>>>(node, Wp1, Wp2, bp2, out, ntiles);
}

// round 7
// speedup vs baseline: 2.8168x; 1.1919x over previous
#include <cuda_runtime.h>
#include <cuda_fp16.h>
#include <cstdint>

// ---------------------------------------------------------------------------
// AutoconstraintModel on GB300 (harness target sm_103 — legacy mma.sync path,
// measured rt~16cyc/SMSP). Tensor-instruction count is the binding resource:
//   2-chain fp16 split:  D = Ahi.Bf + Alo.Bf
//   (A = Ahi + Alo exact in fp16; only B's fp16 rounding ~2^-12 remains)
//  partner (dominant): persistent CTAs, Bf resident in smem, A via cp.async
//      ring (6 slices, distance 5).
//  base:  fp16 2-chain GEMM [B,256]@[256,128] -> g_base, 64-row tiles.
//  label: 3-layer MLP per graph (fp32x2 exact, W staged in smem chunks).
// ---------------------------------------------------------------------------

#define DD 128
#define BSTR 136      // partner B smem row stride (fp16) — conflict-free
#define KSTR 264      // base B smem row stride (fp16), K=256 — conflict-free
#define RING 6        // A ring slices
#define ASTR 20       // A slice row stride (floats)

__device__ float g_base[8192 * 128];   // Base[B][128] scratch (4 MB static)

// ============================ fp32x2 helpers (label) =======================
union F2 { unsigned long long u; float2 f; };

__device__ __forceinline__ void fma2(unsigned long long& d,
                                     unsigned long long a,
                                     unsigned long long b) {
    asm("fma.rn.f32x2 %0, %1, %2, %0;" : "+l"(d) : "l"(a), "l"(b));
}
__device__ __forceinline__ unsigned long long dup2(float w) {
    unsigned long long r;
    asm("mov.b64 %0, {%1, %1};" : "=l"(r) : "f"(w));
    return r;
}

// ============================ HMMA helpers (fp16) ==========================
__device__ __forceinline__ void mma_f16(float* c, const uint32_t* a,
                                        uint32_t b0, uint32_t b1) {
    asm volatile(
        "mma.sync.aligned.m16n8k16.row.col.f32.f16.f16.f32 "
        "{%0,%1,%2,%3}, {%4,%5,%6,%7}, {%8,%9}, {%0,%1,%2,%3};"
        : "+f"(c[0]), "+f"(c[1]), "+f"(c[2]), "+f"(c[3])
        : "r"(a[0]), "r"(a[1]), "r"(a[2]), "r"(a[3]), "r"(b0), "r"(b1));
}

// fp32 pair -> (hi fp16x2, residual fp16x2); A = hi + lo exactly to 2^-23
__device__ __forceinline__ void split2h(float x, float y,
                                        uint32_t& hi, uint32_t& lo) {
    __half2 h = __floats2half2_rn(x, y);
    float2 hf = __half22float2(h);
    __half2 r = __floats2half2_rn(x - hf.x, y - hf.y);
    hi = *reinterpret_cast<uint32_t*>(&h);
    lo = *reinterpret_cast<uint32_t*>(&r);
}

__device__ __forceinline__ uint32_t smem_u32(const void* p) {
    uint32_t a;
    asm("{ .reg .u64 t; cvta.to.shared.u64 t, %1; cvt.u32.u64 %0, t; }"
        : "=r"(a) : "l"(p));
    return a;
}

#define CP_COMMIT() asm volatile("cp.async.commit_group;" ::: "memory")
#define CP_WAIT4()  asm volatile("cp.async.wait_group 4;" ::: "memory")

// ===========================================================================
// base kernel (fp16 2-chain): g_base[g][c] = bp1[c] + [cur|glob]_g @ W1ac.
// 128 blocks x 64 graphs (fills the chip). Bf (fp16, K=256) staged in smem.
// ===========================================================================
__global__ void __launch_bounds__(256) base_kernel(
    const float* __restrict__ node, const float* __restrict__ glob,
    const float* __restrict__ Wp1, const float* __restrict__ bp1, int n_per)
{
    extern __shared__ char smc[];
    __half* Bf  = (__half*)smc;                         // [128 n][KSTR k]
    float* bias = (float*)(Bf + 128 * KSTR);            // [128]

    const int t = threadIdx.x;

    #pragma unroll
    for (int i = 0; i < 128; i++) {                     // 32768 elements
        int idx = t + i * 256;
        int k = idx >> 7, n = idx & 127;                // coalesced over n
        float v = Wp1[(size_t)(k < 128 ? k : k + 128) * 128 + n];
        Bf[n * KSTR + k] = __float2half_rn(v);
    }
    if (t < 128) bias[t] = bp1[t];
    __syncthreads();

    const int w = t >> 5, l = t & 31;
    const int lr = l >> 2, lc = l & 3;
    const int mrow0 = (w & 1) * 32;                     // 64-row tile
    const int ncol0 = (w >> 1) * 32;                    // 4 col bands
    const int g0 = blockIdx.x * 64;

    float acc[2][4][4];
    #pragma unroll
    for (int mt = 0; mt < 2; mt++)
        #pragma unroll
        for (int nt = 0; nt < 4; nt++)
            #pragma unroll
            for (int j = 0; j < 4; j++) acc[mt][nt][j] = 0.f;

    #pragma unroll 2
    for (int kc = 0; kc < 16; kc++) {
        const int kb = kc * 16;
        uint32_t Ah[2][4], Al[2][4];
        #pragma unroll
        for (int mt = 0; mt < 2; mt++) {
            int ga = g0 + mrow0 + mt * 16 + lr;
            int gb = ga + 8;
            const float *pa, *pb;
            if (kb < 128) {
                pa = node + (size_t)((ga + 1) * n_per - 1) * DD + kb + lc * 2;
                pb = node + (size_t)((gb + 1) * n_per - 1) * DD + kb + lc * 2;
            } else {
                pa = glob + (size_t)ga * DD + (kb - 128) + lc * 2;
                pb = glob + (size_t)gb * DD + (kb - 128) + lc * 2;
            }
            float2 v0 = *(const float2*)pa;
            float2 v1 = *(const float2*)pb;
            float2 v2 = *(const float2*)(pa + 8);
            float2 v3 = *(const float2*)(pb + 8);
            split2h(v0.x, v0.y, Ah[mt][0], Al[mt][0]);
            split2h(v1.x, v1.y, Ah[mt][1], Al[mt][1]);
            split2h(v2.x, v2.y, Ah[mt][2], Al[mt][2]);
            split2h(v3.x, v3.y, Ah[mt][3], Al[mt][3]);
        }
        #pragma unroll
        for (int nt = 0; nt < 4; nt++) {
            const __half* bp = Bf + (ncol0 + nt * 8 + lr) * KSTR + kb + lc * 2;
            uint32_t b0 = *(const uint32_t*)bp;
            uint32_t b1 = *(const uint32_t*)(bp + 8);
            #pragma unroll
            for (int mt = 0; mt < 2; mt++) {
                mma_f16(acc[mt][nt], Ah[mt], b0, b1);
                mma_f16(acc[mt][nt], Al[mt], b0, b1);
            }
        }
    }

    #pragma unroll
    for (int mt = 0; mt < 2; mt++) {
        int ga = g0 + mrow0 + mt * 16 + lr;
        #pragma unroll
        for (int nt = 0; nt < 4; nt++) {
            int col = ncol0 + nt * 8 + lc * 2;
            float ba = bias[col], bb = bias[col + 1];
            *(float2*)(g_base + (size_t)ga * 128 + col) =
                make_float2(acc[mt][nt][0] + ba, acc[mt][nt][1] + bb);
            *(float2*)(g_base + (size_t)(ga + 8) * 128 + col) =
                make_float2(acc[mt][nt][2] + ba, acc[mt][nt][3] + bb);
        }
    }
}

// ===========================================================================
// label kernel: 32 graphs/block, fp32x2 exact, W staged in smem chunks.
// ===========================================================================
__global__ void __launch_bounds__(256) label_kernel(
    const float* __restrict__ node, const float* __restrict__ glob,
    const float* __restrict__ Wl1, const float* __restrict__ bl1,
    const float* __restrict__ Wl2, const float* __restrict__ bl2,
    const float* __restrict__ Wl3, const float* __restrict__ bl3,
    const int* __restrict__ pgi, const int* __restrict__ pni,
    int n_per, int NL, float* __restrict__ out)
{
    extern __shared__ float sm[];
    float* xs = sm;                    // [384][34] -> later h2 [128][34]
    float* hs = xs + 384 * 34;         // [128][34]
    float* Ws = hs + 128 * 34;         // [64][128] chunk
    float* w3 = Ws + 64 * 128;         // [128*NL]
    float* b3 = w3 + 128 * NL;         // [NL]

    const int t  = threadIdx.x;
    const int b0 = blockIdx.x * 32;

    #pragma unroll
    for (int i = 0; i < 48; i++) {     // gather 32*384 floats
        int idx = t + i * 256;
        int row = idx >> 7, k = idx & 127;
        int g = row / 3, s = row - g * 3;
        int pg = pgi[b0 + g];
        const float* src;
        if (s == 0)      src = node + (size_t)((pg + 1) * n_per - 1) * DD;
        else if (s == 1) src = node + (size_t)pni[b0 + g] * DD;
        else             src = glob + (size_t)pg * DD;
        xs[(s * 128 + k) * 34 + g] = src[k];
    }
    for (int i = t; i < 128 * NL; i += 256) w3[i] = Wl3[i];
    if (t < NL) b3[t] = bl3[t];

    const int col = t & 127, hf = t >> 7;

    {   // layer 1: K=384, 6 chunks
        F2 acc[8];
        #pragma unroll
        for (int p = 0; p < 8; p++) acc[p].f = make_float2(0.f, 0.f);
        for (int c = 0; c < 6; c++) {
            __syncthreads();
            #pragma unroll
            for (int j = 0; j < 32; j++) {
                int idx = t + j * 256;
                int kk = idx >> 7, cc = idx & 127;
                Ws[kk * 128 + cc] = Wl1[(size_t)(c * 64 + kk) * 128 + cc];
            }
            __syncthreads();
            #pragma unroll 4
            for (int kk = 0; kk < 64; kk++) {
                unsigned long long ww = dup2(Ws[kk * 128 + col]);
                const float* xr = xs + (c * 64 + kk) * 34 + hf * 16;
                #pragma unroll
                for (int p = 0; p < 8; p++)
                    fma2(acc[p].u, *(const unsigned long long*)(xr + 2 * p), ww);
            }
        }
        float b = bl1[col];
        __syncthreads();
        #pragma unroll
        for (int p = 0; p < 8; p++) {
            int g = hf * 16 + 2 * p;
            hs[col * 34 + g]     = fmaxf(acc[p].f.x + b, 0.f);
            hs[col * 34 + g + 1] = fmaxf(acc[p].f.y + b, 0.f);
        }
    }

    {   // layer 2: K=128, 2 chunks
        F2 acc[8];
        #pragma unroll
        for (int p = 0; p < 8; p++) acc[p].f = make_float2(0.f, 0.f);
        for (int c = 0; c < 2; c++) {
            __syncthreads();
            #pragma unroll
            for (int j = 0; j < 32; j++) {
                int idx = t + j * 256;
                int kk = idx >> 7, cc = idx & 127;
                Ws[kk * 128 + cc] = Wl2[(size_t)(c * 64 + kk) * 128 + cc];
            }
            __syncthreads();
            #pragma unroll 4
            for (int kk = 0; kk < 64; kk++) {
                unsigned long long ww = dup2(Ws[kk * 128 + col]);
                const float* xr = hs + (c * 64 + kk) * 34 + hf * 16;
                #pragma unroll
                for (int p = 0; p < 8; p++)
                    fma2(acc[p].u, *(const unsigned long long*)(xr + 2 * p), ww);
            }
        }
        float b = bl2[col];
        __syncthreads();
        #pragma unroll
        for (int p = 0; p < 8; p++) {
            int g = hf * 16 + 2 * p;
            xs[col * 34 + g]     = fmaxf(acc[p].f.x + b, 0.f);
            xs[col * 34 + g + 1] = fmaxf(acc[p].f.y + b, 0.f);
        }
    }
    __syncthreads();

    for (int o = t; o < 32 * NL; o += 256) {   // layer 3
        int g = o / NL, nl = o - g * NL;
        float a = b3[nl];
        #pragma unroll 4
        for (int k = 0; k < 128; k++)
            a += xs[k * 34 + g] * w3[k * NL + nl];
        out[(size_t)(b0 + g) * NL + nl] = a;
    }
}

// ===========================================================================
// partner kernel (dominant): persistent fp16 2-chain HMMA GEMM.
//  - Bf (fp16 Wm) staged ONCE per CTA (35 KB, conflict-free LDS).
//  - A fp32 streamed via cp.async 6-slice ring (prefetch distance 5).
//  - Per tile (128 rows = 2 graphs): 8 k-chunks x 32 HMMA/warp;
//    epilogue relu(D+base).w2 thread-local, quad shfl-reduce, smem combine.
// ===========================================================================
__global__ void __launch_bounds__(256, 2) partner_kernel(
    const float* __restrict__ node, const float* __restrict__ Wp1,
    const float* __restrict__ Wp2, const float* __restrict__ bp2,
    float* __restrict__ out, int ntiles)
{
    extern __shared__ char smc[];
    __half* Bf   = (__half*)smc;                        // [128][BSTR]
    float* Asl   = (float*)(Bf + 128 * BSTR);           // [RING][128][ASTR]
    float* base2 = Asl + RING * 128 * ASTR;             // [256]
    float* w2s   = base2 + 256;                         // [128]
    float* srow  = w2s + 128;                           // [128][2]

    const int t = threadIdx.x;
    const uint32_t asl_u32 = smem_u32(Asl);

    // ---- stage Bf[n][k] = fp16(Wm[k][n]) once per CTA ----
    #pragma unroll
    for (int i = 0; i < 64; i++) {
        int idx = t + i * 256;
        int k = idx >> 7, n = idx & 127;
        Bf[n * BSTR + k] = __float2half_rn(Wp1[(size_t)(128 + k) * 128 + n]);
    }
    if (t < 128) w2s[t] = Wp2[t];
    const float bp2v = bp2[0];

    const int w = t >> 5, l = t & 31;
    const int lr = l >> 2, lc = l & 3;
    const int mrow0 = (w & 3) * 32;
    const int ncol0 = (w >> 2) * 64;
    const int gh = (w & 3) >> 1;

    const int ntloc = (ntiles - (int)blockIdx.x + (int)gridDim.x - 1)
                      / (int)gridDim.x;
    const int nch = ntloc * 8;

    const int row_a = t >> 2;              // cp.async task mapping
    const int c4_a  = (t & 3) * 4;

    auto issue_chunk = [&](int c) {
        int tile = (int)blockIdx.x + (c >> 3) * (int)gridDim.x;
        size_t rb = (size_t)tile * 128;
        int kb = (c & 7) * 16;
        int s = c % RING;
        #pragma unroll
        for (int q = 0; q < 2; q++) {
            int row = row_a + q * 64;
            const float* src = node + (rb + row) * DD + kb + c4_a;
            uint32_t dst = asl_u32
                + (uint32_t)(((s * 128 + row) * ASTR + c4_a) * 4);
            asm volatile("cp.async.cg.shared.global [%0], [%1], 16;"
                         :: "r"(dst), "l"(src));
        }
    };

    #pragma unroll
    for (int c = 0; c < 5; c++) {          // prologue: 5 groups in flight
        if (c < nch) issue_chunk(c);
        CP_COMMIT();
    }

    float acc[2][8][4];

    for (int c = 0; c < nch; c++) {
        CP_WAIT4();
        __syncthreads();                   // slice (c % RING) visible to all

        const int tile = (int)blockIdx.x + (c >> 3) * (int)gridDim.x;
        const int kc = c & 7, s = c % RING;

        if (kc == 0) {
            base2[t] = g_base[(size_t)tile * 256 + t];
            #pragma unroll
            for (int mt = 0; mt < 2; mt++)
                #pragma unroll
                for (int nt = 0; nt < 8; nt++)
                    #pragma unroll
                    for (int j = 0; j < 4; j++) acc[mt][nt][j] = 0.f;
        }

        if (c + 5 < nch) issue_chunk(c + 5);
        CP_COMMIT();

        // ---- A frags from ring slice, split hi/lo fp16 in regs ----
        uint32_t Ah[2][4], Al[2][4];
        const float* ab = Asl + (s * 128 + mrow0 + lr) * ASTR + lc * 2;
        #pragma unroll
        for (int mt = 0; mt < 2; mt++) {
            const float* p = ab + mt * 16 * ASTR;
            float2 v0 = *(const float2*)(p);
            float2 v1 = *(const float2*)(p + 8 * ASTR);
            float2 v2 = *(const float2*)(p + 8);
            float2 v3 = *(const float2*)(p + 8 * ASTR + 8);
            split2h(v0.x, v0.y, Ah[mt][0], Al[mt][0]);
            split2h(v1.x, v1.y, Ah[mt][1], Al[mt][1]);
            split2h(v2.x, v2.y, Ah[mt][2], Al[mt][2]);
            split2h(v3.x, v3.y, Ah[mt][3], Al[mt][3]);
        }

        const int kb = kc * 16;
        #pragma unroll
        for (int nt = 0; nt < 8; nt++) {
            const __half* bp = Bf + (ncol0 + nt * 8 + lr) * BSTR + kb + lc * 2;
            uint32_t b0 = *(const uint32_t*)bp;
            uint32_t b1 = *(const uint32_t*)(bp + 8);
            #pragma unroll
            for (int mt = 0; mt < 2; mt++) {
                mma_f16(acc[mt][nt], Ah[mt], b0, b1);
                mma_f16(acc[mt][nt], Al[mt], b0, b1);
            }
        }

        if (kc == 7) {
            // ---- epilogue: relu(acc+base).w2, quad-reduce, combine ----
            float pr[2][2] = {{0.f, 0.f}, {0.f, 0.f}};
            #pragma unroll
            for (int nt = 0; nt < 8; nt++) {
                int c0 = ncol0 + nt * 8 + lc * 2;
                float wa = w2s[c0], wb = w2s[c0 + 1];
                float ba = base2[gh * 128 + c0], bb = base2[gh * 128 + c0 + 1];
                #pragma unroll
                for (int mt = 0; mt < 2; mt++) {
                    pr[mt][0] += fmaxf(acc[mt][nt][0] + ba, 0.f) * wa
                               + fmaxf(acc[mt][nt][1] + bb, 0.f) * wb;
                    pr[mt][1] += fmaxf(acc[mt][nt][2] + ba, 0.f) * wa
                               + fmaxf(acc[mt][nt][3] + bb, 0.f) * wb;
                }
            }
            #pragma unroll
            for (int o = 1; o <= 2; o <<= 1) {
                pr[0][0] += __shfl_xor_sync(0xffffffffu, pr[0][0], o);
                pr[0][1] += __shfl_xor_sync(0xffffffffu, pr[0][1], o);
                pr[1][0] += __shfl_xor_sync(0xffffffffu, pr[1][0], o);
                pr[1][1] += __shfl_xor_sync(0xffffffffu, pr[1][1], o);
            }
            if (lc == 0) {
                const int cg = w >> 2;
                srow[(mrow0 + lr) * 2 + cg]      = pr[0][0];
                srow[(mrow0 + lr + 8) * 2 + cg]  = pr[0][1];
                srow[(mrow0 + 16 + lr) * 2 + cg] = pr[1][0];
                srow[(mrow0 + 24 + lr) * 2 + cg] = pr[1][1];
            }
            __syncthreads();
            if (t < 128)
                out[(size_t)tile * 128 + t] =
                    srow[t * 2] + srow[t * 2 + 1] + bp2v;
        }
    }
}

// ===========================================================================
extern "C" void kernel_launch(void* const* d_in, const int* in_sizes, int n_in,
                              void* d_out, int out_size)
{
    const float* node = (const float*)d_in[0];
    const float* glob = (const float*)d_in[1];
    const float* Wp1  = (const float*)d_in[2];
    const float* bp1  = (const float*)d_in[3];
    const float* Wp2  = (const float*)d_in[4];
    const float* bp2  = (const float*)d_in[5];
    const float* Wl1  = (const float*)d_in[6];
    const float* bl1  = (const float*)d_in[7];
    const float* Wl2  = (const float*)d_in[8];
    const float* bl2  = (const float*)d_in[9];
    const float* Wl3  = (const float*)d_in[10];
    const float* bl3  = (const float*)d_in[11];
    const int*   pgi  = (const int*)d_in[12];
    const int*   pni  = (const int*)d_in[13];

    const int N     = in_sizes[0] / DD;
    const int B     = in_sizes[1] / DD;
    const int n_per = N / B;            // 64
    const int NL    = in_sizes[11];     // 14
    const int ntiles = N / 128;         // 4096

    float* out = (float*)d_out;

    const size_t smBase = (size_t)(128 * KSTR) * sizeof(__half)
                        + 128 * sizeof(float);
    const size_t smC = (size_t)(384 * 34 + 128 * 34 + 64 * 128 + 128 * NL + NL)
                       * sizeof(float);
    const size_t smP = (size_t)(128 * BSTR) * sizeof(__half)
                     + (size_t)(RING * 128 * ASTR + 256 + 128 + 256)
                       * sizeof(float);

    cudaFuncSetAttribute(base_kernel,    cudaFuncAttributeMaxDynamicSharedMemorySize, (int)smBase);
    cudaFuncSetAttribute(label_kernel,   cudaFuncAttributeMaxDynamicSharedMemorySize, (int)smC);
    cudaFuncSetAttribute(partner_kernel, cudaFuncAttributeMaxDynamicSharedMemorySize, (int)smP);

    base_kernel<<<B / 64, 256, smBase>>>(node, glob, Wp1, bp1, n_per);
    label_kernel<<<B / 32, 256, smC>>>(node, glob, Wl1, bl1, Wl2, bl2,
                                       Wl3, bl3, pgi, pni, n_per, NL,
                                       out + (size_t)N);

    int grid = 2 * 148;                 // persistent, 2 CTAs/SM
    if (grid > ntiles) grid = ntiles;
    partner_kernel<<<grid, 256, smP>>>(node, Wp1, Wp2, bp2, out, ntiles);
}

// round 8
// speedup vs baseline: 3.3199x; 1.1786x over previous
#include <cuda_runtime.h>
#include <cuda_fp16.h>
#include <cstdint>

// ---------------------------------------------------------------------------
// AutoconstraintModel on GB300 (harness target sm_103 — legacy mma.sync).
// fp16 2-chain split (unchanged math, rel_err ~2.5e-4):
//   D = Ahi.Bf + Alo.Bf ; A = Ahi + Alo exact, only B fp16-rounded.
// R8 change: kill the per-chunk lockstep.
//  partner: occ-1 persistent CTAs, WHOLE 64KB A tile double-buffered via one
//           cp.async pass; 2 barriers/tile (was 16); sync-free MMA loop.
//  base:    X staged in one cp.async pass, W fp16 in smem, sync-free MMA.
//  label:   unchanged (fp32x2 exact).
// ---------------------------------------------------------------------------

#define DD 128
#define BSTR 136      // partner/base B smem row stride (fp16) — conflict-free
#define KSTR 264      // base B stride (fp16), K=256 — conflict-free
#define ATSTR 132     // partner A tile row stride (floats, 16B-aligned)
#define XSTR 260      // base X row stride (floats, 16B-aligned)

__device__ float g_base[8192 * 128];   // Base[B][128] scratch (4 MB static)

// ============================ fp32x2 helpers (label) =======================
union F2 { unsigned long long u; float2 f; };

__device__ __forceinline__ void fma2(unsigned long long& d,
                                     unsigned long long a,
                                     unsigned long long b) {
    asm("fma.rn.f32x2 %0, %1, %2, %0;" : "+l"(d) : "l"(a), "l"(b));
}
__device__ __forceinline__ unsigned long long dup2(float w) {
    unsigned long long r;
    asm("mov.b64 %0, {%1, %1};" : "=l"(r) : "f"(w));
    return r;
}

// ============================ HMMA helpers (fp16) ==========================
__device__ __forceinline__ void mma_f16(float* c, const uint32_t* a,
                                        uint32_t b0, uint32_t b1) {
    asm volatile(
        "mma.sync.aligned.m16n8k16.row.col.f32.f16.f16.f32 "
        "{%0,%1,%2,%3}, {%4,%5,%6,%7}, {%8,%9}, {%0,%1,%2,%3};"
        : "+f"(c[0]), "+f"(c[1]), "+f"(c[2]), "+f"(c[3])
        : "r"(a[0]), "r"(a[1]), "r"(a[2]), "r"(a[3]), "r"(b0), "r"(b1));
}

__device__ __forceinline__ void split2h(float x, float y,
                                        uint32_t& hi, uint32_t& lo) {
    __half2 h = __floats2half2_rn(x, y);
    float2 hf = __half22float2(h);
    __half2 r = __floats2half2_rn(x - hf.x, y - hf.y);
    hi = *reinterpret_cast<uint32_t*>(&h);
    lo = *reinterpret_cast<uint32_t*>(&r);
}

__device__ __forceinline__ uint32_t smem_u32(const void* p) {
    uint32_t a;
    asm("{ .reg .u64 t; cvta.to.shared.u64 t, %1; cvt.u32.u64 %0, t; }"
        : "=r"(a) : "l"(p));
    return a;
}

#define CP16(dst_u32, src_ptr) \
    asm volatile("cp.async.cg.shared.global [%0], [%1], 16;" \
                 :: "r"(dst_u32), "l"(src_ptr))
#define CP_COMMIT() asm volatile("cp.async.commit_group;" ::: "memory")
#define CP_WAIT0()  asm volatile("cp.async.wait_group 0;" ::: "memory")
#define CP_WAIT1()  asm volatile("cp.async.wait_group 1;" ::: "memory")

// ===========================================================================
// base kernel: g_base[g][c] = bp1[c] + [cur|glob]_g(256) @ W1ac.
// 128 blocks x 64 graphs, occ 1. X staged via one cp.async pass; W fp16 in
// smem; sync-free 16-chunk MMA loop (fp16 2-chain).
// ===========================================================================
__global__ void __launch_bounds__(256, 1) base_kernel(
    const float* __restrict__ node, const float* __restrict__ glob,
    const float* __restrict__ Wp1, const float* __restrict__ bp1, int n_per)
{
    extern __shared__ char smc[];
    float* Xs   = (float*)smc;                       // [64][XSTR] fp32
    __half* Bf  = (__half*)(Xs + 64 * XSTR);         // [128][KSTR]
    float* bias = (float*)(Bf + 128 * KSTR);         // [128]

    const int t  = threadIdx.x;
    const int g0 = blockIdx.x * 64;
    const uint32_t xs_u32 = smem_u32(Xs);

    // ---- X: cur rows (cols 0-127) + glob rows (cols 128-255), cp.async ----
    #pragma unroll
    for (int i = 0; i < 8; i++) {                    // cur: 2048 float4
        int f = t + i * 256;
        int g = f >> 5, c4 = (f & 31) << 2;
        const float* src = node
            + (size_t)((g0 + g + 1) * n_per - 1) * DD + c4;
        CP16(xs_u32 + (uint32_t)((g * XSTR + c4) * 4), src);
    }
    #pragma unroll
    for (int i = 0; i < 8; i++) {                    // glob: 2048 float4
        int f = t + i * 256;
        int g = f >> 5, c4 = (f & 31) << 2;
        const float* src = glob + (size_t)(g0 + g) * DD + c4;
        CP16(xs_u32 + (uint32_t)((g * XSTR + 128 + c4) * 4), src);
    }
    CP_COMMIT();

    // ---- Bf[n][k] = fp16(W1ac[k][n]) (plain stores) ----
    #pragma unroll
    for (int i = 0; i < 128; i++) {
        int idx = t + i * 256;
        int k = idx >> 7, n = idx & 127;
        Bf[n * KSTR + k] =
            __float2half_rn(Wp1[(size_t)(k < 128 ? k : k + 128) * 128 + n]);
    }
    if (t < 128) bias[t] = bp1[t];
    CP_WAIT0();
    __syncthreads();

    const int w = t >> 5, l = t & 31;
    const int lr = l >> 2, lc = l & 3;
    const int mrow0 = (w & 1) * 32;                  // 2 row bands
    const int ncol0 = (w >> 1) * 32;                 // 4 col bands

    float acc[2][4][4];
    #pragma unroll
    for (int mt = 0; mt < 2; mt++)
        #pragma unroll
        for (int nt = 0; nt < 4; nt++)
            #pragma unroll
            for (int j = 0; j < 4; j++) acc[mt][nt][j] = 0.f;

    const float* ab = Xs + (mrow0 + lr) * XSTR + lc * 2;

    #pragma unroll
    for (int kc = 0; kc < 16; kc++) {
        const int kb = kc * 16;
        uint32_t Ah[2][4], Al[2][4];
        #pragma unroll
        for (int mt = 0; mt < 2; mt++) {
            const float* p = ab + mt * 16 * XSTR + kb;
            float2 v0 = *(const float2*)(p);
            float2 v1 = *(const float2*)(p + 8 * XSTR);
            float2 v2 = *(const float2*)(p + 8);
            float2 v3 = *(const float2*)(p + 8 * XSTR + 8);
            split2h(v0.x, v0.y, Ah[mt][0], Al[mt][0]);
            split2h(v1.x, v1.y, Ah[mt][1], Al[mt][1]);
            split2h(v2.x, v2.y, Ah[mt][2], Al[mt][2]);
            split2h(v3.x, v3.y, Ah[mt][3], Al[mt][3]);
        }
        #pragma unroll
        for (int nt = 0; nt < 4; nt++) {
            const __half* bp = Bf + (ncol0 + nt * 8 + lr) * KSTR + kb + lc * 2;
            uint32_t b0 = *(const uint32_t*)bp;
            uint32_t b1 = *(const uint32_t*)(bp + 8);
            #pragma unroll
            for (int mt = 0; mt < 2; mt++) {
                mma_f16(acc[mt][nt], Ah[mt], b0, b1);
                mma_f16(acc[mt][nt], Al[mt], b0, b1);
            }
        }
    }

    #pragma unroll
    for (int mt = 0; mt < 2; mt++) {
        int ga = g0 + mrow0 + mt * 16 + lr;
        #pragma unroll
        for (int nt = 0; nt < 4; nt++) {
            int col = ncol0 + nt * 8 + lc * 2;
            float ba = bias[col], bb = bias[col + 1];
            *(float2*)(g_base + (size_t)ga * 128 + col) =
                make_float2(acc[mt][nt][0] + ba, acc[mt][nt][1] + bb);
            *(float2*)(g_base + (size_t)(ga + 8) * 128 + col) =
                make_float2(acc[mt][nt][2] + ba, acc[mt][nt][3] + bb);
        }
    }
}

// ===========================================================================
// label kernel: 32 graphs/block, fp32x2 exact, W staged in smem chunks.
// ===========================================================================
__global__ void __launch_bounds__(256) label_kernel(
    const float* __restrict__ node, const float* __restrict__ glob,
    const float* __restrict__ Wl1, const float* __restrict__ bl1,
    const float* __restrict__ Wl2, const float* __restrict__ bl2,
    const float* __restrict__ Wl3, const float* __restrict__ bl3,
    const int* __restrict__ pgi, const int* __restrict__ pni,
    int n_per, int NL, float* __restrict__ out)
{
    extern __shared__ float sm[];
    float* xs = sm;                    // [384][34] -> later h2 [128][34]
    float* hs = xs + 384 * 34;         // [128][34]
    float* Ws = hs + 128 * 34;         // [64][128] chunk
    float* w3 = Ws + 64 * 128;         // [128*NL]
    float* b3 = w3 + 128 * NL;         // [NL]

    const int t  = threadIdx.x;
    const int b0 = blockIdx.x * 32;

    #pragma unroll
    for (int i = 0; i < 48; i++) {     // gather 32*384 floats
        int idx = t + i * 256;
        int row = idx >> 7, k = idx & 127;
        int g = row / 3, s = row - g * 3;
        int pg = pgi[b0 + g];
        const float* src;
        if (s == 0)      src = node + (size_t)((pg + 1) * n_per - 1) * DD;
        else if (s == 1) src = node + (size_t)pni[b0 + g] * DD;
        else             src = glob + (size_t)pg * DD;
        xs[(s * 128 + k) * 34 + g] = src[k];
    }
    for (int i = t; i < 128 * NL; i += 256) w3[i] = Wl3[i];
    if (t < NL) b3[t] = bl3[t];

    const int col = t & 127, hf = t >> 7;

    {   // layer 1: K=384, 6 chunks
        F2 acc[8];
        #pragma unroll
        for (int p = 0; p < 8; p++) acc[p].f = make_float2(0.f, 0.f);
        for (int c = 0; c < 6; c++) {
            __syncthreads();
            #pragma unroll
            for (int j = 0; j < 32; j++) {
                int idx = t + j * 256;
                int kk = idx >> 7, cc = idx & 127;
                Ws[kk * 128 + cc] = Wl1[(size_t)(c * 64 + kk) * 128 + cc];
            }
            __syncthreads();
            #pragma unroll 4
            for (int kk = 0; kk < 64; kk++) {
                unsigned long long ww = dup2(Ws[kk * 128 + col]);
                const float* xr = xs + (c * 64 + kk) * 34 + hf * 16;
                #pragma unroll
                for (int p = 0; p < 8; p++)
                    fma2(acc[p].u, *(const unsigned long long*)(xr + 2 * p), ww);
            }
        }
        float b = bl1[col];
        __syncthreads();
        #pragma unroll
        for (int p = 0; p < 8; p++) {
            int g = hf * 16 + 2 * p;
            hs[col * 34 + g]     = fmaxf(acc[p].f.x + b, 0.f);
            hs[col * 34 + g + 1] = fmaxf(acc[p].f.y + b, 0.f);
        }
    }

    {   // layer 2: K=128, 2 chunks
        F2 acc[8];
        #pragma unroll
        for (int p = 0; p < 8; p++) acc[p].f = make_float2(0.f, 0.f);
        for (int c = 0; c < 2; c++) {
            __syncthreads();
            #pragma unroll
            for (int j = 0; j < 32; j++) {
                int idx = t + j * 256;
                int kk = idx >> 7, cc = idx & 127;
                Ws[kk * 128 + cc] = Wl2[(size_t)(c * 64 + kk) * 128 + cc];
            }
            __syncthreads();
            #pragma unroll 4
            for (int kk = 0; kk < 64; kk++) {
                unsigned long long ww = dup2(Ws[kk * 128 + col]);
                const float* xr = hs + (c * 64 + kk) * 34 + hf * 16;
                #pragma unroll
                for (int p = 0; p < 8; p++)
                    fma2(acc[p].u, *(const unsigned long long*)(xr + 2 * p), ww);
            }
        }
        float b = bl2[col];
        __syncthreads();
        #pragma unroll
        for (int p = 0; p < 8; p++) {
            int g = hf * 16 + 2 * p;
            xs[col * 34 + g]     = fmaxf(acc[p].f.x + b, 0.f);
            xs[col * 34 + g + 1] = fmaxf(acc[p].f.y + b, 0.f);
        }
    }
    __syncthreads();

    for (int o = t; o < 32 * NL; o += 256) {   // layer 3
        int g = o / NL, nl = o - g * NL;
        float a = b3[nl];
        #pragma unroll 4
        for (int k = 0; k < 128; k++)
            a += xs[k * 34 + g] * w3[k * NL + nl];
        out[(size_t)(b0 + g) * NL + nl] = a;
    }
}

// ===========================================================================
// partner kernel (dominant): occ-1 persistent fp16 2-chain HMMA GEMM.
//  - Bf (fp16 Wm, 35KB) staged once per CTA.
//  - WHOLE A tile (64KB fp32, contiguous in gmem) + its 1KB base slice
//    double-buffered via cp.async; 2 barriers per tile, sync-free MMA loop.
// ===========================================================================
__global__ void __launch_bounds__(256, 1) partner_kernel(
    const float* __restrict__ node, const float* __restrict__ Wp1,
    const float* __restrict__ Wp2, const float* __restrict__ bp2,
    float* __restrict__ out, int ntiles)
{
    extern __shared__ char smc[];
    __half* Bf  = (__half*)smc;                      // [128][BSTR]
    float* Ab0  = (float*)(Bf + 128 * BSTR);         // [2][128][ATSTR]
    float* bs0  = Ab0 + 2 * 128 * ATSTR;             // [2][256]
    float* w2s  = bs0 + 512;                         // [128]
    float* srow = w2s + 128;                         // [128][2]

    const int t = threadIdx.x;
    const uint32_t ab_u32 = smem_u32(Ab0);
    const uint32_t bs_u32 = smem_u32(bs0);

    // ---- stage Bf[n][k] = fp16(Wm[k][n]) once per CTA ----
    #pragma unroll
    for (int i = 0; i < 64; i++) {
        int idx = t + i * 256;
        int k = idx >> 7, n = idx & 127;
        Bf[n * BSTR + k] = __float2half_rn(Wp1[(size_t)(128 + k) * 128 + n]);
    }
    if (t < 128) w2s[t] = Wp2[t];
    const float bp2v = bp2[0];

    const int w = t >> 5, l = t & 31;
    const int lr = l >> 2, lc = l & 3;
    const int mrow0 = (w & 3) * 32;
    const int ncol0 = (w >> 2) * 64;
    const int gh = (w & 3) >> 1;

    const int ntloc = (ntiles - (int)blockIdx.x + (int)gridDim.x - 1)
                      / (int)gridDim.x;

    // issue the full A tile + base slice for local tile index q
    auto issue_tile = [&](int q) {
        int tq = (int)blockIdx.x + q * (int)gridDim.x;
        if (tq < ntiles) {
            const float* src = node + (size_t)tq * (128 * DD);
            const uint32_t du = ab_u32
                + (uint32_t)((q & 1) * 128 * ATSTR * 4);
            #pragma unroll
            for (int i = 0; i < 16; i++) {           // 4096 float4
                int f = t + i * 256;
                int row = f >> 5, c4 = (f & 31) << 2;
                CP16(du + (uint32_t)((row * ATSTR + c4) * 4), src + f * 4);
            }
            if (t < 64) {
                const float* sb = g_base + (size_t)tq * 256 + t * 4;
                CP16(bs_u32 + (uint32_t)(((q & 1) * 256 + t * 4) * 4), sb);
            }
        }
    };

    issue_tile(0); CP_COMMIT();
    issue_tile(1); CP_COMMIT();

    for (int q = 0; q < ntloc; q++) {
        const int tq = (int)blockIdx.x + q * (int)gridDim.x;

        CP_WAIT1();                    // tile q's group complete
        __syncthreads();

        const float* Abuf  = Ab0 + (q & 1) * (128 * ATSTR);
        const float* base2 = bs0 + (q & 1) * 256;

        float acc[2][8][4];
        #pragma unroll
        for (int mt = 0; mt < 2; mt++)
            #pragma unroll
            for (int nt = 0; nt < 8; nt++)
                #pragma unroll
                for (int j = 0; j < 4; j++) acc[mt][nt][j] = 0.f;

        const float* ab = Abuf + (mrow0 + lr) * ATSTR + lc * 2;

        #pragma unroll
        for (int kc = 0; kc < 8; kc++) {             // sync-free MMA stream
            const int kb = kc * 16;
            uint32_t Ah[2][4], Al[2][4];
            #pragma unroll
            for (int mt = 0; mt < 2; mt++) {
                const float* p = ab + mt * 16 * ATSTR + kb;
                float2 v0 = *(const float2*)(p);
                float2 v1 = *(const float2*)(p + 8 * ATSTR);
                float2 v2 = *(const float2*)(p + 8);
                float2 v3 = *(const float2*)(p + 8 * ATSTR + 8);
                split2h(v0.x, v0.y, Ah[mt][0], Al[mt][0]);
                split2h(v1.x, v1.y, Ah[mt][1], Al[mt][1]);
                split2h(v2.x, v2.y, Ah[mt][2], Al[mt][2]);
                split2h(v3.x, v3.y, Ah[mt][3], Al[mt][3]);
            }
            #pragma unroll
            for (int nt = 0; nt < 8; nt++) {
                const __half* bp = Bf + (ncol0 + nt * 8 + lr) * BSTR
                                      + kb + lc * 2;
                uint32_t b0 = *(const uint32_t*)bp;
                uint32_t b1 = *(const uint32_t*)(bp + 8);
                #pragma unroll
                for (int mt = 0; mt < 2; mt++) {
                    mma_f16(acc[mt][nt], Ah[mt], b0, b1);
                    mma_f16(acc[mt][nt], Al[mt], b0, b1);
                }
            }
        }

        // ---- epilogue: relu(acc+base).w2, quad-reduce, combine ----
        float pr[2][2] = {{0.f, 0.f}, {0.f, 0.f}};
        #pragma unroll
        for (int nt = 0; nt < 8; nt++) {
            int c0 = ncol0 + nt * 8 + lc * 2;
            float wa = w2s[c0], wb = w2s[c0 + 1];
            float ba = base2[gh * 128 + c0], bb = base2[gh * 128 + c0 + 1];
            #pragma unroll
            for (int mt = 0; mt < 2; mt++) {
                pr[mt][0] += fmaxf(acc[mt][nt][0] + ba, 0.f) * wa
                           + fmaxf(acc[mt][nt][1] + bb, 0.f) * wb;
                pr[mt][1] += fmaxf(acc[mt][nt][2] + ba, 0.f) * wa
                           + fmaxf(acc[mt][nt][3] + bb, 0.f) * wb;
            }
        }
        #pragma unroll
        for (int o = 1; o <= 2; o <<= 1) {
            pr[0][0] += __shfl_xor_sync(0xffffffffu, pr[0][0], o);
            pr[0][1] += __shfl_xor_sync(0xffffffffu, pr[0][1], o);
            pr[1][0] += __shfl_xor_sync(0xffffffffu, pr[1][0], o);
            pr[1][1] += __shfl_xor_sync(0xffffffffu, pr[1][1], o);
        }
        if (lc == 0) {
            const int cg = w >> 2;
            srow[(mrow0 + lr) * 2 + cg]      = pr[0][0];
            srow[(mrow0 + lr + 8) * 2 + cg]  = pr[0][1];
            srow[(mrow0 + 16 + lr) * 2 + cg] = pr[1][0];
            srow[(mrow0 + 24 + lr) * 2 + cg] = pr[1][1];
        }
        __syncthreads();               // srow ready AND A buffer free
        if (t < 128)
            out[(size_t)tq * 128 + t] = srow[t * 2] + srow[t * 2 + 1] + bp2v;

        issue_tile(q + 2);             // refill the buffer just vacated
        CP_COMMIT();
    }
}

// ===========================================================================
extern "C" void kernel_launch(void* const* d_in, const int* in_sizes, int n_in,
                              void* d_out, int out_size)
{
    const float* node = (const float*)d_in[0];
    const float* glob = (const float*)d_in[1];
    const float* Wp1  = (const float*)d_in[2];
    const float* bp1  = (const float*)d_in[3];
    const float* Wp2  = (const float*)d_in[4];
    const float* bp2  = (const float*)d_in[5];
    const float* Wl1  = (const float*)d_in[6];
    const float* bl1  = (const float*)d_in[7];
    const float* Wl2  = (const float*)d_in[8];
    const float* bl2  = (const float*)d_in[9];
    const float* Wl3  = (const float*)d_in[10];
    const float* bl3  = (const float*)d_in[11];
    const int*   pgi  = (const int*)d_in[12];
    const int*   pni  = (const int*)d_in[13];

    const int N     = in_sizes[0] / DD;
    const int B     = in_sizes[1] / DD;
    const int n_per = N / B;            // 64
    const int NL    = in_sizes[11];     // 14
    const int ntiles = N / 128;         // 4096

    float* out = (float*)d_out;

    const size_t smBase = (size_t)(64 * XSTR) * sizeof(float)
                        + (size_t)(128 * KSTR) * sizeof(__half)
                        + 128 * sizeof(float);
    const size_t smC = (size_t)(384 * 34 + 128 * 34 + 64 * 128 + 128 * NL + NL)
                       * sizeof(float);
    const size_t smP = (size_t)(128 * BSTR) * sizeof(__half)
                     + (size_t)(2 * 128 * ATSTR + 512 + 128 + 256)
                       * sizeof(float);

    cudaFuncSetAttribute(base_kernel,    cudaFuncAttributeMaxDynamicSharedMemorySize, (int)smBase);
    cudaFuncSetAttribute(label_kernel,   cudaFuncAttributeMaxDynamicSharedMemorySize, (int)smC);
    cudaFuncSetAttribute(partner_kernel, cudaFuncAttributeMaxDynamicSharedMemorySize, (int)smP);

    base_kernel<<<B / 64, 256, smBase>>>(node, glob, Wp1, bp1, n_per);
    label_kernel<<<B / 32, 256, smC>>>(node, glob, Wl1, bl1, Wl2, bl2,
                                       Wl3, bl3, pgi, pni, n_per, NL,
                                       out + (size_t)N);

    int grid = 148;                     // occ-1 persistent, 1 CTA/SM
    if (grid > ntiles) grid = ntiles;
    partner_kernel<<<grid, 148 ? 256 : 256, smP>>>(node, Wp1, Wp2, bp2,
                                                   out, ntiles);
}

// round 9
// speedup vs baseline: 3.8281x; 1.1531x over previous
#include <cuda_runtime.h>
#include <cuda_fp16.h>
#include <cstdint>

// ---------------------------------------------------------------------------
// AutoconstraintModel on GB300 (harness target sm_103 — legacy mma.sync).
// R9: partner -> single-chain fp16 (D = f16(A).f16(B)); predicted rel_err
//     ~3.5e-4 (sqrt2 x measured B-only 2.47e-4). Base keeps 2-chain.
//     base+label fused into one aux kernel (occ 2) to overlap them.
//  partner: occ-1 persistent, whole 64KB A tile double-buffered (cp.async),
//           2 barriers/tile, sync-free MMA stream.
// ---------------------------------------------------------------------------

#define DD 128
#define BSTR 136      // partner B smem row stride (fp16) — conflict-free
#define KSTR 264      // base B stride (fp16), K=256 — conflict-free
#define ATSTR 132     // partner A tile row stride (floats)
#define XSTR 260      // base X row stride (floats)

__device__ float g_base[8192 * 128];   // Base[B][128] scratch (4 MB static)

// ============================ fp32x2 helpers (label) =======================
union F2 { unsigned long long u; float2 f; };

__device__ __forceinline__ void fma2(unsigned long long& d,
                                     unsigned long long a,
                                     unsigned long long b) {
    asm("fma.rn.f32x2 %0, %1, %2, %0;" : "+l"(d) : "l"(a), "l"(b));
}
__device__ __forceinline__ unsigned long long dup2(float w) {
    unsigned long long r;
    asm("mov.b64 %0, {%1, %1};" : "=l"(r) : "f"(w));
    return r;
}

// ============================ HMMA helpers (fp16) ==========================
__device__ __forceinline__ void mma_f16(float* c, const uint32_t* a,
                                        uint32_t b0, uint32_t b1) {
    asm volatile(
        "mma.sync.aligned.m16n8k16.row.col.f32.f16.f16.f32 "
        "{%0,%1,%2,%3}, {%4,%5,%6,%7}, {%8,%9}, {%0,%1,%2,%3};"
        : "+f"(c[0]), "+f"(c[1]), "+f"(c[2]), "+f"(c[3])
        : "r"(a[0]), "r"(a[1]), "r"(a[2]), "r"(a[3]), "r"(b0), "r"(b1));
}

__device__ __forceinline__ uint32_t cvt2h(float x, float y) {
    __half2 h = __floats2half2_rn(x, y);
    return *reinterpret_cast<uint32_t*>(&h);
}
__device__ __forceinline__ void split2h(float x, float y,
                                        uint32_t& hi, uint32_t& lo) {
    __half2 h = __floats2half2_rn(x, y);
    float2 hf = __half22float2(h);
    __half2 r = __floats2half2_rn(x - hf.x, y - hf.y);
    hi = *reinterpret_cast<uint32_t*>(&h);
    lo = *reinterpret_cast<uint32_t*>(&r);
}

__device__ __forceinline__ uint32_t smem_u32(const void* p) {
    uint32_t a;
    asm("{ .reg .u64 t; cvta.to.shared.u64 t, %1; cvt.u32.u64 %0, t; }"
        : "=r"(a) : "l"(p));
    return a;
}

#define CP16(dst_u32, src_ptr) \
    asm volatile("cp.async.cg.shared.global [%0], [%1], 16;" \
                 :: "r"(dst_u32), "l"(src_ptr))
#define CP_COMMIT() asm volatile("cp.async.commit_group;" ::: "memory")
#define CP_WAIT0()  asm volatile("cp.async.wait_group 0;" ::: "memory")
#define CP_WAIT1()  asm volatile("cp.async.wait_group 1;" ::: "memory")

// ===========================================================================
// aux kernel: blocks [0, nBase) do base (32 graphs each, fp16 2-chain HMMA);
// blocks [nBase, nBase + nLab) do label (32 graphs each, fp32x2 exact).
// Both branches <= 110KB smem -> occ 2: base and label overlap across SMs.
// ===========================================================================
__global__ void __launch_bounds__(256, 2) aux_kernel(
    const float* __restrict__ node, const float* __restrict__ glob,
    const float* __restrict__ Wp1, const float* __restrict__ bp1,
    const float* __restrict__ Wl1, const float* __restrict__ bl1,
    const float* __restrict__ Wl2, const float* __restrict__ bl2,
    const float* __restrict__ Wl3, const float* __restrict__ bl3,
    const int* __restrict__ pgi, const int* __restrict__ pni,
    int n_per, int NL, float* __restrict__ out_label, int nBase)
{
    extern __shared__ char smc[];
    const int t = threadIdx.x;

    if ((int)blockIdx.x < nBase) {
        // ================= base branch: 32 graphs ==========================
        float* Xs   = (float*)smc;                   // [32][XSTR]
        __half* Bf  = (__half*)(Xs + 32 * XSTR);     // [128][KSTR]
        float* bias = (float*)(Bf + 128 * KSTR);     // [128]

        const int g0 = (int)blockIdx.x * 32;
        const uint32_t xs_u32 = smem_u32(Xs);

        #pragma unroll
        for (int i = 0; i < 4; i++) {                // cur: 1024 float4
            int f = t + i * 256;
            int g = f >> 5, c4 = (f & 31) << 2;
            const float* src = node
                + (size_t)((g0 + g + 1) * n_per - 1) * DD + c4;
            CP16(xs_u32 + (uint32_t)((g * XSTR + c4) * 4), src);
        }
        #pragma unroll
        for (int i = 0; i < 4; i++) {                // glob: 1024 float4
            int f = t + i * 256;
            int g = f >> 5, c4 = (f & 31) << 2;
            const float* src = glob + (size_t)(g0 + g) * DD + c4;
            CP16(xs_u32 + (uint32_t)((g * XSTR + 128 + c4) * 4), src);
        }
        CP_COMMIT();

        #pragma unroll
        for (int i = 0; i < 128; i++) {              // Bf[n][k] = f16(W[k][n])
            int idx = t + i * 256;
            int k = idx >> 7, n = idx & 127;
            Bf[n * KSTR + k] = __float2half_rn(
                Wp1[(size_t)(k < 128 ? k : k + 128) * 128 + n]);
        }
        if (t < 128) bias[t] = bp1[t];
        CP_WAIT0();
        __syncthreads();

        const int w = t >> 5, l = t & 31;
        const int lr = l >> 2, lc = l & 3;
        const int mrow0 = (w & 1) * 16;              // 2 row bands of 16
        const int ncol0 = (w >> 1) * 32;             // 4 col bands

        float acc[4][4];
        #pragma unroll
        for (int nt = 0; nt < 4; nt++)
            #pragma unroll
            for (int j = 0; j < 4; j++) acc[nt][j] = 0.f;

        const float* ab = Xs + (mrow0 + lr) * XSTR + lc * 2;

        #pragma unroll
        for (int kc = 0; kc < 16; kc++) {
            const int kb = kc * 16;
            uint32_t Ah[4], Al[4];
            const float* p = ab + kb;
            float2 v0 = *(const float2*)(p);
            float2 v1 = *(const float2*)(p + 8 * XSTR);
            float2 v2 = *(const float2*)(p + 8);
            float2 v3 = *(const float2*)(p + 8 * XSTR + 8);
            split2h(v0.x, v0.y, Ah[0], Al[0]);
            split2h(v1.x, v1.y, Ah[1], Al[1]);
            split2h(v2.x, v2.y, Ah[2], Al[2]);
            split2h(v3.x, v3.y, Ah[3], Al[3]);
            #pragma unroll
            for (int nt = 0; nt < 4; nt++) {
                const __half* bp = Bf + (ncol0 + nt * 8 + lr) * KSTR
                                      + kb + lc * 2;
                uint32_t b0 = *(const uint32_t*)bp;
                uint32_t b1 = *(const uint32_t*)(bp + 8);
                mma_f16(acc[nt], Ah, b0, b1);
                mma_f16(acc[nt], Al, b0, b1);
            }
        }

        const int ga = g0 + mrow0 + lr;
        #pragma unroll
        for (int nt = 0; nt < 4; nt++) {
            int col = ncol0 + nt * 8 + lc * 2;
            float ba = bias[col], bb = bias[col + 1];
            *(float2*)(g_base + (size_t)ga * 128 + col) =
                make_float2(acc[nt][0] + ba, acc[nt][1] + bb);
            *(float2*)(g_base + (size_t)(ga + 8) * 128 + col) =
                make_float2(acc[nt][2] + ba, acc[nt][3] + bb);
        }
        return;
    }

    // ==================== label branch: 32 graphs ==========================
    {
        float* sm = (float*)smc;
        float* xs = sm;                    // [384][34] -> later h2 [128][34]
        float* hs = xs + 384 * 34;         // [128][34]
        float* Ws = hs + 128 * 34;         // [64][128] chunk
        float* w3 = Ws + 64 * 128;         // [128*NL]
        float* b3 = w3 + 128 * NL;         // [NL]

        const int b0 = ((int)blockIdx.x - nBase) * 32;

        #pragma unroll
        for (int i = 0; i < 48; i++) {     // gather 32*384 floats
            int idx = t + i * 256;
            int row = idx >> 7, k = idx & 127;
            int g = row / 3, s = row - g * 3;
            int pg = pgi[b0 + g];
            const float* src;
            if (s == 0)      src = node + (size_t)((pg + 1) * n_per - 1) * DD;
            else if (s == 1) src = node + (size_t)pni[b0 + g] * DD;
            else             src = glob + (size_t)pg * DD;
            xs[(s * 128 + k) * 34 + g] = src[k];
        }
        for (int i = t; i < 128 * NL; i += 256) w3[i] = Wl3[i];
        if (t < NL) b3[t] = bl3[t];

        const int col = t & 127, hf = t >> 7;

        {   // layer 1: K=384, 6 chunks
            F2 acc[8];
            #pragma unroll
            for (int p = 0; p < 8; p++) acc[p].f = make_float2(0.f, 0.f);
            for (int c = 0; c < 6; c++) {
                __syncthreads();
                #pragma unroll
                for (int j = 0; j < 32; j++) {
                    int idx = t + j * 256;
                    int kk = idx >> 7, cc = idx & 127;
                    Ws[kk * 128 + cc] = Wl1[(size_t)(c * 64 + kk) * 128 + cc];
                }
                __syncthreads();
                #pragma unroll 4
                for (int kk = 0; kk < 64; kk++) {
                    unsigned long long ww = dup2(Ws[kk * 128 + col]);
                    const float* xr = xs + (c * 64 + kk) * 34 + hf * 16;
                    #pragma unroll
                    for (int p = 0; p < 8; p++)
                        fma2(acc[p].u,
                             *(const unsigned long long*)(xr + 2 * p), ww);
                }
            }
            float b = bl1[col];
            __syncthreads();
            #pragma unroll
            for (int p = 0; p < 8; p++) {
                int g = hf * 16 + 2 * p;
                hs[col * 34 + g]     = fmaxf(acc[p].f.x + b, 0.f);
                hs[col * 34 + g + 1] = fmaxf(acc[p].f.y + b, 0.f);
            }
        }

        {   // layer 2: K=128, 2 chunks
            F2 acc[8];
            #pragma unroll
            for (int p = 0; p < 8; p++) acc[p].f = make_float2(0.f, 0.f);
            for (int c = 0; c < 2; c++) {
                __syncthreads();
                #pragma unroll
                for (int j = 0; j < 32; j++) {
                    int idx = t + j * 256;
                    int kk = idx >> 7, cc = idx & 127;
                    Ws[kk * 128 + cc] = Wl2[(size_t)(c * 64 + kk) * 128 + cc];
                }
                __syncthreads();
                #pragma unroll 4
                for (int kk = 0; kk < 64; kk++) {
                    unsigned long long ww = dup2(Ws[kk * 128 + col]);
                    const float* xr = hs + (c * 64 + kk) * 34 + hf * 16;
                    #pragma unroll
                    for (int p = 0; p < 8; p++)
                        fma2(acc[p].u,
                             *(const unsigned long long*)(xr + 2 * p), ww);
                }
            }
            float b = bl2[col];
            __syncthreads();
            #pragma unroll
            for (int p = 0; p < 8; p++) {
                int g = hf * 16 + 2 * p;
                xs[col * 34 + g]     = fmaxf(acc[p].f.x + b, 0.f);
                xs[col * 34 + g + 1] = fmaxf(acc[p].f.y + b, 0.f);
            }
        }
        __syncthreads();

        for (int o = t; o < 32 * NL; o += 256) {   // layer 3
            int g = o / NL, nl = o - g * NL;
            float a = b3[nl];
            #pragma unroll 4
            for (int k = 0; k < 128; k++)
                a += xs[k * 34 + g] * w3[k * NL + nl];
            out_label[(size_t)(b0 + g) * NL + nl] = a;
        }
    }
}

// ===========================================================================
// partner kernel (dominant): occ-1 persistent fp16 SINGLE-chain HMMA GEMM.
//  - Bf (fp16 Wm) staged once per CTA; whole A tile double-buffered.
//  - Per tile: 8 sync-free k-chunks x 16 HMMA/warp; 2 barriers/tile.
// ===========================================================================
__global__ void __launch_bounds__(256, 1) partner_kernel(
    const float* __restrict__ node, const float* __restrict__ Wp1,
    const float* __restrict__ Wp2, const float* __restrict__ bp2,
    float* __restrict__ out, int ntiles)
{
    extern __shared__ char smc[];
    __half* Bf  = (__half*)smc;                      // [128][BSTR]
    float* Ab0  = (float*)(Bf + 128 * BSTR);         // [2][128][ATSTR]
    float* bs0  = Ab0 + 2 * 128 * ATSTR;             // [2][256]
    float* w2s  = bs0 + 512;                         // [128]
    float* srow = w2s + 128;                         // [128][2]

    const int t = threadIdx.x;
    const uint32_t ab_u32 = smem_u32(Ab0);
    const uint32_t bs_u32 = smem_u32(bs0);

    #pragma unroll
    for (int i = 0; i < 64; i++) {                   // Bf[n][k] = f16(Wm[k][n])
        int idx = t + i * 256;
        int k = idx >> 7, n = idx & 127;
        Bf[n * BSTR + k] = __float2half_rn(Wp1[(size_t)(128 + k) * 128 + n]);
    }
    if (t < 128) w2s[t] = Wp2[t];
    const float bp2v = bp2[0];

    const int w = t >> 5, l = t & 31;
    const int lr = l >> 2, lc = l & 3;
    const int mrow0 = (w & 3) * 32;
    const int ncol0 = (w >> 2) * 64;
    const int gh = (w & 3) >> 1;

    const int ntloc = (ntiles - (int)blockIdx.x + (int)gridDim.x - 1)
                      / (int)gridDim.x;

    auto issue_tile = [&](int q) {
        int tq = (int)blockIdx.x + q * (int)gridDim.x;
        if (tq < ntiles) {
            const float* src = node + (size_t)tq * (128 * DD);
            const uint32_t du = ab_u32
                + (uint32_t)((q & 1) * 128 * ATSTR * 4);
            #pragma unroll
            for (int i = 0; i < 16; i++) {           // 4096 float4
                int f = t + i * 256;
                int row = f >> 5, c4 = (f & 31) << 2;
                CP16(du + (uint32_t)((row * ATSTR + c4) * 4), src + f * 4);
            }
            if (t < 64) {
                const float* sb = g_base + (size_t)tq * 256 + t * 4;
                CP16(bs_u32 + (uint32_t)(((q & 1) * 256 + t * 4) * 4), sb);
            }
        }
    };

    issue_tile(0); CP_COMMIT();
    issue_tile(1); CP_COMMIT();

    for (int q = 0; q < ntloc; q++) {
        const int tq = (int)blockIdx.x + q * (int)gridDim.x;

        CP_WAIT1();
        __syncthreads();

        const float* Abuf  = Ab0 + (q & 1) * (128 * ATSTR);
        const float* base2 = bs0 + (q & 1) * 256;

        float acc[2][8][4];
        #pragma unroll
        for (int mt = 0; mt < 2; mt++)
            #pragma unroll
            for (int nt = 0; nt < 8; nt++)
                #pragma unroll
                for (int j = 0; j < 4; j++) acc[mt][nt][j] = 0.f;

        const float* ab = Abuf + (mrow0 + lr) * ATSTR + lc * 2;

        #pragma unroll
        for (int kc = 0; kc < 8; kc++) {             // sync-free MMA stream
            const int kb = kc * 16;
            uint32_t Ah[2][4];
            #pragma unroll
            for (int mt = 0; mt < 2; mt++) {
                const float* p = ab + mt * 16 * ATSTR + kb;
                float2 v0 = *(const float2*)(p);
                float2 v1 = *(const float2*)(p + 8 * ATSTR);
                float2 v2 = *(const float2*)(p + 8);
                float2 v3 = *(const float2*)(p + 8 * ATSTR + 8);
                Ah[mt][0] = cvt2h(v0.x, v0.y);
                Ah[mt][1] = cvt2h(v1.x, v1.y);
                Ah[mt][2] = cvt2h(v2.x, v2.y);
                Ah[mt][3] = cvt2h(v3.x, v3.y);
            }
            #pragma unroll
            for (int nt = 0; nt < 8; nt++) {
                const __half* bp = Bf + (ncol0 + nt * 8 + lr) * BSTR
                                      + kb + lc * 2;
                uint32_t b0 = *(const uint32_t*)bp;
                uint32_t b1 = *(const uint32_t*)(bp + 8);
                mma_f16(acc[0][nt], Ah[0], b0, b1);
                mma_f16(acc[1][nt], Ah[1], b0, b1);
            }
        }

        // ---- epilogue: relu(acc+base).w2, quad-reduce, combine ----
        float pr[2][2] = {{0.f, 0.f}, {0.f, 0.f}};
        #pragma unroll
        for (int nt = 0; nt < 8; nt++) {
            int c0 = ncol0 + nt * 8 + lc * 2;
            float wa = w2s[c0], wb = w2s[c0 + 1];
            float ba = base2[gh * 128 + c0], bb = base2[gh * 128 + c0 + 1];
            #pragma unroll
            for (int mt = 0; mt < 2; mt++) {
                pr[mt][0] += fmaxf(acc[mt][nt][0] + ba, 0.f) * wa
                           + fmaxf(acc[mt][nt][1] + bb, 0.f) * wb;
                pr[mt][1] += fmaxf(acc[mt][nt][2] + ba, 0.f) * wa
                           + fmaxf(acc[mt][nt][3] + bb, 0.f) * wb;
            }
        }
        #pragma unroll
        for (int o = 1; o <= 2; o <<= 1) {
            pr[0][0] += __shfl_xor_sync(0xffffffffu, pr[0][0], o);
            pr[0][1] += __shfl_xor_sync(0xffffffffu, pr[0][1], o);
            pr[1][0] += __shfl_xor_sync(0xffffffffu, pr[1][0], o);
            pr[1][1] += __shfl_xor_sync(0xffffffffu, pr[1][1], o);
        }
        if (lc == 0) {
            const int cg = w >> 2;
            srow[(mrow0 + lr) * 2 + cg]      = pr[0][0];
            srow[(mrow0 + lr + 8) * 2 + cg]  = pr[0][1];
            srow[(mrow0 + 16 + lr) * 2 + cg] = pr[1][0];
            srow[(mrow0 + 24 + lr) * 2 + cg] = pr[1][1];
        }
        __syncthreads();               // srow ready AND A buffer free
        if (t < 128)
            out[(size_t)tq * 128 + t] = srow[t * 2] + srow[t * 2 + 1] + bp2v;

        issue_tile(q + 2);             // refill the buffer just vacated
        CP_COMMIT();
    }
}

// ===========================================================================
extern "C" void kernel_launch(void* const* d_in, const int* in_sizes, int n_in,
                              void* d_out, int out_size)
{
    const float* node = (const float*)d_in[0];
    const float* glob = (const float*)d_in[1];
    const float* Wp1  = (const float*)d_in[2];
    const float* bp1  = (const float*)d_in[3];
    const float* Wp2  = (const float*)d_in[4];
    const float* bp2  = (const float*)d_in[5];
    const float* Wl1  = (const float*)d_in[6];
    const float* bl1  = (const float*)d_in[7];
    const float* Wl2  = (const float*)d_in[8];
    const float* bl2  = (const float*)d_in[9];
    const float* Wl3  = (const float*)d_in[10];
    const float* bl3  = (const float*)d_in[11];
    const int*   pgi  = (const int*)d_in[12];
    const int*   pni  = (const int*)d_in[13];

    const int N     = in_sizes[0] / DD;
    const int B     = in_sizes[1] / DD;
    const int n_per = N / B;            // 64
    const int NL    = in_sizes[11];     // 14
    const int ntiles = N / 128;         // 4096

    float* out = (float*)d_out;

    const size_t smBase = (size_t)(32 * XSTR) * sizeof(float)
                        + (size_t)(128 * KSTR) * sizeof(__half)
                        + 128 * sizeof(float);
    const size_t smLab  = (size_t)(384 * 34 + 128 * 34 + 64 * 128
                                   + 128 * NL + NL) * sizeof(float);
    const size_t smAux  = smBase > smLab ? smBase : smLab;
    const size_t smP = (size_t)(128 * BSTR) * sizeof(__half)
                     + (size_t)(2 * 128 * ATSTR + 512 + 128 + 256)
                       * sizeof(float);

    cudaFuncSetAttribute(aux_kernel,     cudaFuncAttributeMaxDynamicSharedMemorySize, (int)smAux);
    cudaFuncSetAttribute(partner_kernel, cudaFuncAttributeMaxDynamicSharedMemorySize, (int)smP);

    const int nBase = B / 32;           // 256 base blocks (32 graphs each)
    const int nLab  = B / 32;           // 256 label blocks
    aux_kernel<<<nBase + nLab, 256, smAux>>>(node, glob, Wp1, bp1,
                                             Wl1, bl1, Wl2, bl2, Wl3, bl3,
                                             pgi, pni, n_per, NL,
                                             out + (size_t)N, nBase);

    int grid = 148;                     // occ-1 persistent
    if (grid > ntiles) grid = ntiles;
    partner_kernel<<<grid, 256, smP>>>(node, Wp1, Wp2, bp2, out, ntiles);
}